// round 14
// baseline (speedup 1.0000x reference)
#include <cuda_runtime.h>
#include <cuda_bf16.h>
#include <cuda_fp16.h>
#include <math.h>
#include <stdint.h>

#define BATCH 4
#define NTOK  4096      // N = 64*64
#define CDIM  256
#define NH    8
#define HD    32
#define RESHW 64
#define PLP   64        // pooled length (8*8)
#define TBLN  4096
#define BH    (BATCH*NH)
#define EPSF  1.1920929e-07f

// ---------------- scratch (device globals; no dynamic alloc) ----------------
__device__ float g_q   [BATCH*NTOK*CDIM];        // q_norm fp32
__device__ float g_kv  [BATCH*NTOK*2*CDIM];      // kv; k half normalized
__device__ float g_sr  [BATCH*NTOK*CDIM];
__device__ float g_gate[BATCH*NTOK*NH];
__device__ float g_cpb [TBLN*NH];
__device__ __half g_xh [BATCH*NTOK*CDIM];        // x fp16
__device__ __half g_wh [1280*CDIM];              // weights hi
__device__ __half g_wl [1280*CDIM];              // weights lo
__device__ __half g_ph [BATCH*PLP*CDIM];         // pooled+LN fp16
__device__ __half g_ah [BATCH*NTOK*CDIM];        // attention out fp16
__device__ __half g_qsh[BATCH*NTOK*CDIM];        // q_scaled hi
__device__ __half g_qsl[BATCH*NTOK*CDIM];        // q_scaled lo
__device__ __half g_kph[BATCH*PLP*CDIM];         // k_pool norm hi
__device__ __half g_kpl[BATCH*PLP*CDIM];         // k_pool norm lo
__device__ __half g_vph[BATCH*PLP*CDIM];         // v_pool fp16

__device__ __forceinline__ float warp_sum(float v) {
#pragma unroll
    for (int o = 16; o; o >>= 1) v += __shfl_xor_sync(0xffffffffu, v, o);
    return v;
}
__device__ __forceinline__ float warp_max(float v) {
#pragma unroll
    for (int o = 16; o; o >>= 1) v = fmaxf(v, __shfl_xor_sync(0xffffffffu, v, o));
    return v;
}

// ================= helpers ==================================================
__device__ __forceinline__ uint32_t smem_u32(const void* p) {
    uint32_t a;
    asm("{ .reg .u64 t; cvta.to.shared.u64 t, %1; cvt.u32.u64 %0, t; }"
        : "=r"(a) : "l"(p));
    return a;
}
__device__ __forceinline__ void ldsm_x4(uint32_t* r, uint32_t addr) {
    asm volatile("ldmatrix.sync.aligned.m8n8.x4.shared.b16 {%0,%1,%2,%3}, [%4];"
                 : "=r"(r[0]), "=r"(r[1]), "=r"(r[2]), "=r"(r[3]) : "r"(addr));
}
__device__ __forceinline__ void ldsm_x2(uint32_t* r, uint32_t addr) {
    asm volatile("ldmatrix.sync.aligned.m8n8.x2.shared.b16 {%0,%1}, [%2];"
                 : "=r"(r[0]), "=r"(r[1]) : "r"(addr));
}
__device__ __forceinline__ void mma_f16(float* c, const uint32_t* a,
                                        const uint32_t* b) {
    asm volatile(
        "mma.sync.aligned.m16n8k16.row.col.f32.f16.f16.f32 "
        "{%0,%1,%2,%3}, {%4,%5,%6,%7}, {%8,%9}, {%0,%1,%2,%3};"
        : "+f"(c[0]), "+f"(c[1]), "+f"(c[2]), "+f"(c[3])
        : "r"(a[0]), "r"(a[1]), "r"(a[2]), "r"(a[3]), "r"(b[0]), "r"(b[1]));
}
__device__ __forceinline__ void cp16(uint32_t dst, const void* src) {
    asm volatile("cp.async.cg.shared.global [%0], [%1], 16;"
                 :: "r"(dst), "l"(src));
}
#define CP_COMMIT() asm volatile("cp.async.commit_group;" ::: "memory")
#define CP_WAIT0()  asm volatile("cp.async.wait_group 0;" ::: "memory")
#define CP_WAIT1()  asm volatile("cp.async.wait_group 1;" ::: "memory")

// ---------------- x convert (fp16) + gating (single x read) ------------------
__global__ void __launch_bounds__(256)
conv_x_gate(const float* __restrict__ x, const float* __restrict__ wg,
            const float* __restrict__ wg0, const float* __restrict__ wg1) {
    int t = blockIdx.x * 8 + (threadIdx.x >> 5);
    int lane = threadIdx.x & 31;
    const float* xt = x + (size_t)t * CDIM;
    float4 xa = *(const float4*)(xt + lane * 8);
    float4 xb = *(const float4*)(xt + lane * 8 + 4);
    __half2 h0 = __floats2half2_rn(xa.x, xa.y);
    __half2 h1 = __floats2half2_rn(xa.z, xa.w);
    __half2 h2 = __floats2half2_rn(xb.x, xb.y);
    __half2 h3 = __floats2half2_rn(xb.z, xb.w);
    uint4 u;
    u.x = *(uint32_t*)&h0; u.y = *(uint32_t*)&h1;
    u.z = *(uint32_t*)&h2; u.w = *(uint32_t*)&h3;
    *(uint4*)(g_xh + (size_t)t * CDIM + lane * 8) = u;
    float d[10];
#pragma unroll
    for (int i = 0; i < 10; i++) {
        const float* wr = (i < 4) ? wg + i * CDIM
                        : (i < 8) ? wg1 + (i - 4) * CDIM
                                  : wg0 + (i - 8) * CDIM;
        float4 wa = *(const float4*)(wr + lane * 8);
        float4 wb = *(const float4*)(wr + lane * 8 + 4);
        float s = xa.x * wa.x + xa.y * wa.y + xa.z * wa.z + xa.w * wa.w
                + xb.x * wb.x + xb.y * wb.y + xb.z * wb.z + xb.w * wb.w;
        d[i] = warp_sum(s);
    }
    float m0 = fmaxf(fmaxf(d[0], d[1]), fmaxf(d[2], d[3]));
    float e[4], se = 0.f;
#pragma unroll
    for (int i = 0; i < 4; i++) { e[i] = expf(d[i] - m0); se += e[i]; }
    float gsm[4];
#pragma unroll
    for (int i = 0; i < 4; i++) gsm[i] = e[i] / se;
    int i1 = 0;
#pragma unroll
    for (int i = 1; i < 4; i++) if (gsm[i] > gsm[i1]) i1 = i;
    int i2 = -1;
#pragma unroll
    for (int i = 0; i < 4; i++) {
        if (i == i1) continue;
        if (i2 < 0 || gsm[i] > gsm[i2]) i2 = i;
    }
    float rs = fmaxf(gsm[i1] + gsm[i2], EPSF);
    float routed[4];
#pragma unroll
    for (int i = 0; i < 4; i++)
        routed[i] = (i == i1 || i == i2) ? gsm[i] / rs * 2.f : 0.f;
    float m1 = fmaxf(fmaxf(d[4], d[5]), fmaxf(d[6], d[7]));
    float es[4], ss = 0.f;
#pragma unroll
    for (int i = 0; i < 4; i++) { es[i] = expf(d[4 + i] - m1); ss += es[i]; }
    float shg[4];
#pragma unroll
    for (int i = 0; i < 4; i++) shg[i] = es[i] / ss * 4.f;
    float m2 = fmaxf(d[8], d[9]);
    float e8 = expf(d[8] - m2), e9 = expf(d[9] - m2);
    float w00 = e8 / (e8 + e9) * 2.f;
    float w01 = e9 / (e8 + e9) * 2.f;
    if (lane < NH) {
        float v = (lane < 4) ? w00 * shg[lane] : w01 * routed[lane - 4];
        g_gate[(size_t)t * NH + lane] = v;
    }
}

// ---------------- all-weights fp16 hi/lo convert -----------------------------
__global__ void __launch_bounds__(256)
conv_w(const float* __restrict__ qw, const float* __restrict__ kvw,
       const float* __restrict__ srw, const float* __restrict__ pjw) {
    int i = blockIdx.x * 256 + threadIdx.x;   // float4 index, 81920 total
    int row = i >> 6;
    const float4* src;
    int off;
    if (row < 256)       { src = (const float4*)qw;  off = i; }
    else if (row < 768)  { src = (const float4*)kvw; off = i - 256 * 64; }
    else if (row < 1024) { src = (const float4*)srw; off = i - 768 * 64; }
    else                 { src = (const float4*)pjw; off = i - 1024 * 64; }
    float4 v = src[off];
    __half a0 = __float2half_rn(v.x), a1 = __float2half_rn(v.y);
    __half a2 = __float2half_rn(v.z), a3 = __float2half_rn(v.w);
    __half b0 = __float2half_rn(v.x - __half2float(a0));
    __half b1 = __float2half_rn(v.y - __half2float(a1));
    __half b2 = __float2half_rn(v.z - __half2float(a2));
    __half b3 = __float2half_rn(v.w - __half2float(a3));
    ushort4 H, L;
    H.x = *(uint16_t*)&a0; H.y = *(uint16_t*)&a1;
    H.z = *(uint16_t*)&a2; H.w = *(uint16_t*)&a3;
    L.x = *(uint16_t*)&b0; L.y = *(uint16_t*)&b1;
    L.z = *(uint16_t*)&b2; L.w = *(uint16_t*)&b3;
    ((ushort4*)g_wh)[i] = H;
    ((ushort4*)g_wl)[i] = L;
}

// ================= 3-stage pipelined 2-term fp16 GEMM =======================
// MODE 0: fused q/kv/sr + q/k L2 norm epilogue.  MODE 1: plain.  MODE 2: pooled
// kv epilogue (normalize k per head -> kph/kpl fp16, v -> vph fp16).
#define MATSZ (128 * 40)
#define STAGEB (3 * MATSZ * 2)
#define GSMEM (3 * STAGEB)          // 92160 B

template<int MODE>
__global__ void __launch_bounds__(256, 2)
gemm_f16(const __half* __restrict__ A,
         const __half* __restrict__ Wh, const __half* __restrict__ Wl,
         float* __restrict__ C0, float* __restrict__ C1, float* __restrict__ C2,
         const float* __restrict__ b0, const float* __restrict__ b1,
         const float* __restrict__ b2, int ldc0,
         const float* __restrict__ temp, const float* __restrict__ qe) {
    extern __shared__ uint16_t sd[];
    const int bm = blockIdx.y * 128, bn = blockIdx.x * 128;
    const int tid = threadIdx.x, lane = tid & 31, wid = tid >> 5;
    const int wm = (wid & 3) * 32, wn = (wid >> 2) * 64;
    float acc[2][8][4] = {};

    const __half* gsrc[3] = {
        A + (size_t)bm * 256, Wh + (size_t)bn * 256, Wl + (size_t)bn * 256};

    const int ldrow = tid >> 2, ldpart = tid & 3;
    const uint32_t sb0 = smem_u32(sd);
    uint32_t aAdr[2];
#pragma unroll
    for (int i = 0; i < 2; i++)
        aAdr[i] = sb0 + 2 * ((wm + i * 16 + (lane & 15)) * 40 + (lane >> 4) * 8);
    uint32_t bAdr[4];
    {
        int m = lane >> 3;
#pragma unroll
        for (int jp = 0; jp < 4; jp++)
            bAdr[jp] = sb0 + 2 * (MATSZ + (wn + jp * 16 + (m >> 1) * 8 +
                                           (lane & 7)) * 40 + (m & 1) * 8);
    }

#define GLOAD(stage, ko) do {                                                  \
    const int nb_ = (stage) * 3 * MATSZ;                                       \
    _Pragma("unroll")                                                          \
    for (int m_ = 0; m_ < 3; m_++)                                             \
        _Pragma("unroll")                                                      \
        for (int s_ = 0; s_ < 2; s_++) {                                       \
            int row_ = ldrow + s_ * 64;                                        \
            cp16(smem_u32(sd + nb_ + m_ * MATSZ + row_ * 40 + ldpart * 8),     \
                 gsrc[m_] + (size_t)row_ * 256 + (ko) + ldpart * 8);           \
        }                                                                      \
    CP_COMMIT();                                                               \
} while (0)

    GLOAD(0, 0);
    GLOAD(1, 32);

#pragma unroll
    for (int kc = 0; kc < 8; kc++) {
        const int stg = kc % 3;
        const uint32_t so = (uint32_t)stg * STAGEB;
        if (kc < 7) { CP_WAIT1(); } else { CP_WAIT0(); }
        __syncthreads();
        if (kc < 6) GLOAD((kc + 2) % 3, (kc + 2) * 32);
#pragma unroll
        for (int ks = 0; ks < 2; ks++) {
            const uint32_t so2 = so + ks * 32;
            uint32_t ah[2][4];
            ldsm_x4(ah[0], aAdr[0] + so2);
            ldsm_x4(ah[1], aAdr[1] + so2);
#pragma unroll
            for (int jp = 0; jp < 4; jp++) {
                uint32_t bh[4], bl[4];
                ldsm_x4(bh, bAdr[jp] + so2);
                ldsm_x4(bl, bAdr[jp] + so2 + 2 * MATSZ);
#pragma unroll
                for (int i = 0; i < 2; i++) {
                    mma_f16(acc[i][jp * 2], ah[i], bh);
                    mma_f16(acc[i][jp * 2], ah[i], bl);
                    mma_f16(acc[i][jp * 2 + 1], ah[i], bh + 2);
                    mma_f16(acc[i][jp * 2 + 1], ah[i], bl + 2);
                }
            }
        }
    }
#undef GLOAD

    if (MODE == 0) {
        const int r = bn >> 7;
        const bool isQ = r < 2, isK = (r == 2 || r == 3), isSR = r >= 6;
        const float* bias = isQ ? b0 : (r < 6 ? b1 : b2);
        const int cb = isQ ? bn : (r < 6 ? bn - 256 : bn - 768);
#pragma unroll
        for (int i = 0; i < 2; i++)
#pragma unroll
            for (int j = 0; j < 8; j++) {
                int col = cb + wn + j * 8 + (lane & 3) * 2;
                float bb0 = bias[col], bb1 = bias[col + 1];
                acc[i][j][0] += bb0; acc[i][j][1] += bb1;
                acc[i][j][2] += bb0; acc[i][j][3] += bb1;
                if (isSR) {
#pragma unroll
                    for (int t = 0; t < 4; t++) {
                        float v = acc[i][j][t];
                        acc[i][j][t] =
                            0.5f * v * (1.0f + erff(v * 0.70710678118654752f));
                    }
                }
            }
        if (isQ || isK) {
            float* sums = (float*)sd;
            sums[tid] = 0.f; sums[tid + 256] = 0.f;
            __syncthreads();
#pragma unroll
            for (int i = 0; i < 2; i++)
#pragma unroll
                for (int half = 0; half < 2; half++)
#pragma unroll
                    for (int hg = 0; hg < 2; hg++) {
                        float p = 0.f;
#pragma unroll
                        for (int j = hg * 4; j < hg * 4 + 4; j++)
                            p += acc[i][j][half * 2] * acc[i][j][half * 2] +
                                 acc[i][j][half * 2 + 1] * acc[i][j][half * 2 + 1];
                        p += __shfl_xor_sync(0xffffffffu, p, 1);
                        p += __shfl_xor_sync(0xffffffffu, p, 2);
                        if ((lane & 3) == 0) {
                            int rr = wm + i * 16 + (lane >> 2) + half * 8;
                            atomicAdd(&sums[rr * 4 + (wn >> 5) + hg], p);
                        }
                    }
            __syncthreads();
            if (isQ) {
                float sp[2];
#pragma unroll
                for (int hg = 0; hg < 2; hg++)
                    sp[hg] = log1pf(expf(temp[((bn + wn) >> 5) + hg]));
                float sls[2][2];
#pragma unroll
                for (int i = 0; i < 2; i++)
#pragma unroll
                    for (int half = 0; half < 2; half++) {
                        int row = wm + i * 16 + (lane >> 2) + half * 8;
                        int n = (bm + row) & (NTOK - 1);
                        int yq = n >> 6, xq = n & 63;
                        int chh = min(yq + 1, 63) - max(yq - 1, 0) + 1;
                        int cww = min(xq + 1, 63) - max(xq - 1, 0) + 1;
                        sls[i][half] = logf((float)(chh * cww + PLP));
                    }
#pragma unroll
                for (int i = 0; i < 2; i++)
#pragma unroll
                    for (int j = 0; j < 8; j++) {
                        int hg = j >> 2;
                        int gcol = bn + wn + j * 8 + (lane & 3) * 2;
                        float qe0 = qe[gcol];
                        float qe1 = qe[gcol + 1];
#pragma unroll
                        for (int half = 0; half < 2; half++) {
                            int row = wm + i * 16 + (lane >> 2) + half * 8;
                            float inv = 1.f /
                                fmaxf(sqrtf(sums[row * 4 + (wn >> 5) + hg]), EPSF);
                            float q0 = acc[i][j][half * 2] * inv;
                            float q1 = acc[i][j][half * 2 + 1] * inv;
                            size_t go = (size_t)(bm + row) * 256 + gcol;
                            float2 f2; f2.x = q0; f2.y = q1;
                            *(float2*)(g_q + go) = f2;
                            float m = sp[hg] * sls[i][half];
                            float s0 = (q0 + qe0) * m, s1 = (q1 + qe1) * m;
                            __half hh0 = __float2half_rn(s0);
                            __half hh1 = __float2half_rn(s1);
                            *(__half2*)(g_qsh + go) = __halves2half2(hh0, hh1);
                            *(__half2*)(g_qsl + go) = __halves2half2(
                                __float2half_rn(s0 - __half2float(hh0)),
                                __float2half_rn(s1 - __half2float(hh1)));
                        }
                    }
            } else {
#pragma unroll
                for (int i = 0; i < 2; i++)
#pragma unroll
                    for (int j = 0; j < 8; j++) {
                        int hg = j >> 2;
                        int gcol = cb + wn + j * 8 + (lane & 3) * 2;
#pragma unroll
                        for (int half = 0; half < 2; half++) {
                            int row = wm + i * 16 + (lane >> 2) + half * 8;
                            float inv = 1.f /
                                fmaxf(sqrtf(sums[row * 4 + (wn >> 5) + hg]), EPSF);
                            float2 f2;
                            f2.x = acc[i][j][half * 2] * inv;
                            f2.y = acc[i][j][half * 2 + 1] * inv;
                            *(float2*)(g_kv + (size_t)(bm + row) * 512 + gcol) = f2;
                        }
                    }
            }
        } else {
            float* C = isSR ? C2 : C1;
            int ldc = isSR ? 256 : 512;
#pragma unroll
            for (int i = 0; i < 2; i++) {
                int r0 = bm + wm + i * 16 + (lane >> 2);
#pragma unroll
                for (int j = 0; j < 8; j++) {
                    int col = cb + wn + j * 8 + (lane & 3) * 2;
                    float2 o01; o01.x = acc[i][j][0]; o01.y = acc[i][j][1];
                    float2 o23; o23.x = acc[i][j][2]; o23.y = acc[i][j][3];
                    *(float2*)(C + (size_t)r0 * ldc + col) = o01;
                    *(float2*)(C + (size_t)(r0 + 8) * ldc + col) = o23;
                }
            }
        }
        return;
    }
    if (MODE == 2) {
        const bool isKp = bn < 256;
#pragma unroll
        for (int i = 0; i < 2; i++)
#pragma unroll
            for (int j = 0; j < 8; j++) {
                int col = bn + wn + j * 8 + (lane & 3) * 2;
                float bb0 = b0[col], bb1 = b0[col + 1];
                acc[i][j][0] += bb0; acc[i][j][1] += bb1;
                acc[i][j][2] += bb0; acc[i][j][3] += bb1;
            }
        if (isKp) {
            float* sums = (float*)sd;
            sums[tid] = 0.f; sums[tid + 256] = 0.f;
            __syncthreads();
#pragma unroll
            for (int i = 0; i < 2; i++)
#pragma unroll
                for (int half = 0; half < 2; half++)
#pragma unroll
                    for (int hg = 0; hg < 2; hg++) {
                        float p = 0.f;
#pragma unroll
                        for (int j = hg * 4; j < hg * 4 + 4; j++)
                            p += acc[i][j][half * 2] * acc[i][j][half * 2] +
                                 acc[i][j][half * 2 + 1] * acc[i][j][half * 2 + 1];
                        p += __shfl_xor_sync(0xffffffffu, p, 1);
                        p += __shfl_xor_sync(0xffffffffu, p, 2);
                        if ((lane & 3) == 0) {
                            int rr = wm + i * 16 + (lane >> 2) + half * 8;
                            atomicAdd(&sums[rr * 4 + (wn >> 5) + hg], p);
                        }
                    }
            __syncthreads();
#pragma unroll
            for (int i = 0; i < 2; i++)
#pragma unroll
                for (int j = 0; j < 8; j++) {
                    int hg = j >> 2;
                    int gcol = bn + wn + j * 8 + (lane & 3) * 2;
#pragma unroll
                    for (int half = 0; half < 2; half++) {
                        int row = wm + i * 16 + (lane >> 2) + half * 8;
                        float inv = 1.f /
                            fmaxf(sqrtf(sums[row * 4 + (wn >> 5) + hg]), EPSF);
                        float k0 = acc[i][j][half * 2] * inv;
                        float k1 = acc[i][j][half * 2 + 1] * inv;
                        __half hh0 = __float2half_rn(k0);
                        __half hh1 = __float2half_rn(k1);
                        size_t go = (size_t)(bm + row) * 256 + gcol;
                        *(__half2*)(g_kph + go) = __halves2half2(hh0, hh1);
                        *(__half2*)(g_kpl + go) = __halves2half2(
                            __float2half_rn(k0 - __half2float(hh0)),
                            __float2half_rn(k1 - __half2float(hh1)));
                    }
                }
        } else {
#pragma unroll
            for (int i = 0; i < 2; i++)
#pragma unroll
                for (int j = 0; j < 8; j++) {
                    int gcol = bn - 256 + wn + j * 8 + (lane & 3) * 2;
#pragma unroll
                    for (int half = 0; half < 2; half++) {
                        int row = wm + i * 16 + (lane >> 2) + half * 8;
                        *(__half2*)(g_vph + (size_t)(bm + row) * 256 + gcol) =
                            __floats2half2_rn(acc[i][j][half * 2],
                                              acc[i][j][half * 2 + 1]);
                    }
                }
        }
        return;
    }
    // MODE 1
#pragma unroll
    for (int i = 0; i < 2; i++) {
        int r0 = bm + wm + i * 16 + (lane >> 2);
#pragma unroll
        for (int j = 0; j < 8; j++) {
            int col = bn + wn + j * 8 + (lane & 3) * 2;
            float bb0 = b0[col], bb1 = b0[col + 1];
            float2 o01; o01.x = acc[i][j][0] + bb0; o01.y = acc[i][j][1] + bb1;
            float2 o23; o23.x = acc[i][j][2] + bb0; o23.y = acc[i][j][3] + bb1;
            *(float2*)(C0 + (size_t)r0 * ldc0 + col) = o01;
            *(float2*)(C0 + (size_t)(r0 + 8) * ldc0 + col) = o23;
        }
    }
}

// ---------------- 8x8 avg pool + LayerNorm (writes fp16) ---------------------
__global__ void __launch_bounds__(256)
pool_ln(const float* __restrict__ gw, const float* __restrict__ gb) {
    int bp = blockIdx.x;
    int b = bp >> 6, p = bp & 63;
    int py = p >> 3, px = p & 7;
    int c = threadIdx.x;
    const float* base = g_sr + (size_t)b * NTOK * CDIM;
    float s = 0.f;
    for (int iy = 0; iy < 8; iy++) {
        int y = py * 8 + iy;
        for (int ix = 0; ix < 8; ix++) {
            int n = y * RESHW + px * 8 + ix;
            s += base[(size_t)n * CDIM + c];
        }
    }
    float val = s * (1.0f / 64.0f);
    __shared__ float red[256];
    red[c] = val; __syncthreads();
    for (int st = 128; st > 0; st >>= 1) { if (c < st) red[c] += red[c + st]; __syncthreads(); }
    float mu = red[0] * (1.0f / 256.0f);
    __syncthreads();
    float dv = val - mu;
    red[c] = dv * dv; __syncthreads();
    for (int st = 128; st > 0; st >>= 1) { if (c < st) red[c] += red[c + st]; __syncthreads(); }
    float var = red[0] * (1.0f / 256.0f);
    float ov = dv * rsqrtf(var + 1e-5f) * gw[c] + gb[c];
    g_ph[(size_t)bp * CDIM + c] = __float2half_rn(ov);
}

// ---------------- cpb MLP ----------------------------------------------------
__global__ void __launch_bounds__(128)
cpb_kernel(const float* __restrict__ tbl, const float* __restrict__ w1,
           const float* __restrict__ b1, const float* __restrict__ w2,
           const float* __restrict__ b2) {
    int row = blockIdx.x;
    int tid = threadIdx.x;
    float t0 = tbl[row * 2 + 0], t1 = tbl[row * 2 + 1];
    float acc[8] = {};
    for (int j = tid; j < 512; j += 128) {
        float hv = fmaxf(t0 * w1[2 * j] + t1 * w1[2 * j + 1] + b1[j], 0.f);
#pragma unroll
        for (int o = 0; o < 8; o++) acc[o] += hv * w2[o * 512 + j];
    }
#pragma unroll
    for (int o = 0; o < 8; o++) acc[o] = warp_sum(acc[o]);
    __shared__ float sh[4][8];
    int wp = tid >> 5, lane = tid & 31;
    if (lane == 0)
#pragma unroll
        for (int o = 0; o < 8; o++) sh[wp][o] = acc[o];
    __syncthreads();
    if (tid < 8)
        g_cpb[(size_t)row * 8 + tid] =
            sh[0][tid] + sh[1][tid] + sh[2][tid] + sh[3][tid] + b2[tid];
}

// ================ attn: fused S-mma + local logits + softmax + AV ============
// 256 threads (8 warps), 32 tokens/block, 4 tokens per warp.
// __launch_bounds__(256,2) => 128 regs/thread, no spills; 2 CTAs/SM.
#define AKW 0
#define AVW 3366
#define AQS 6732
#define AQN 7788
#define ALG 8844               // lg [32][84]: 0..63 S, 64..72 local, 73..81 lt
#define ALT 11532              // 9*33=297 pad 300
#define ALO 11832              // lout [32][33]
#define AFLOATS 12888
// halves: Ph 2304, Pl 2304, Vt 2304, Qh 1280, Ql 1280, Kp_h 2560, Kp_l 2560
#define ASMEMB (AFLOATS * 4 + 14592 * 2)   // 80736 B

__global__ void __launch_bounds__(256, 2)
attn_soft(const float* __restrict__ rpb, const float* __restrict__ lt,
          const float* __restrict__ lb, const int* __restrict__ rel_idx) {
    extern __shared__ float sh[];
    float* Kw  = sh + AKW;
    float* Vw  = sh + AVW;
    float* qss = sh + AQS;
    float* qns = sh + AQN;
    float* lg  = sh + ALG;
    float* lts = sh + ALT;
    float* lout = sh + ALO;
    __half* Ph  = (__half*)(sh + AFLOATS);
    __half* Pl  = Ph + 2304;
    __half* Vt  = Pl + 2304;
    __half* Qh  = Vt + 2304;    // [32][40]
    __half* Ql  = Qh + 1280;
    __half* Kph = Ql + 1280;    // [64][40]
    __half* Kpl = Kph + 2560;
    int blk = blockIdx.x;
    int ntile = blk & 127;
    int hh = (blk >> 7) & 7;
    int b = blk >> 10;
    int tid = threadIdx.x, w = tid >> 5, lane = tid & 31;
    int y = ntile >> 1, x0 = (ntile & 1) << 5;

    for (int i = tid; i < 3264; i += 256) {
        int vec = i >> 5, d = i & 31;
        int r = vec / 34, c = vec - r * 34;
        int yy = y + r - 1, xx = x0 - 1 + c;
        float kv0 = 0.f, vv0 = 0.f;
        if ((unsigned)yy < 64u && (unsigned)xx < 64u) {
            size_t base = ((size_t)(b * NTOK + yy * 64 + xx)) * 512 + hh * 32 + d;
            kv0 = g_kv[base];
            vv0 = g_kv[base + 256];
        }
        Kw[vec * 33 + d] = kv0;
        Vw[vec * 33 + d] = vv0;
    }
    for (int i = tid; i < 288; i += 256) {
        int d = i / 9, l = i - d * 9;
        lts[l * 33 + d] = lt[hh * 288 + i];
    }
    // stage pooled V^T, pooled K hi/lo
    for (int i = tid; i < 2048; i += 256) {
        int p = i >> 5, d = i & 31;
        size_t src = ((size_t)(b * PLP + p)) * CDIM + hh * HD + d;
        Vt[d * 72 + p] = g_vph[src];
        Kph[p * 40 + d] = g_kph[src];
        Kpl[p * 40 + d] = g_kpl[src];
    }
    // q staging: 4 tokens/warp
#pragma unroll
    for (int tk = 0; tk < 4; tk++) {
        int row = w * 4 + tk;
        int n = ntile * 32 + row;
        size_t qoff = ((size_t)(b * NTOK + n)) * 256 + hh * 32 + lane;
        __half qh_ = g_qsh[qoff], ql_ = g_qsl[qoff];
        Qh[row * 40 + lane] = qh_;
        Ql[row * 40 + lane] = ql_;
        qss[row * 33 + lane] = __half2float(qh_) + __half2float(ql_);
        qns[row * 33 + lane] = g_q[qoff];
    }
    __syncthreads();

    // local + learnable logits: 4 tokens/warp, lanes 0..17 each
#pragma unroll
    for (int tk = 0; tk < 4; tk++) {
        int row = w * 4 + tk;
        int n = ntile * 32 + row;
        int xl = n & 31;
        int o = lane;
        if (o < 18) {
            const float* kr;
            const float* qr;
            float bias;
            int slot;
            if (o < 9) {
                int r = o / 3, dc = o - r * 3;
                kr = Kw + (r * 34 + xl + dc) * 33;
                qr = qss + row * 33;
                bias = rpb[hh * 9 + o];
                slot = 64 + o;
            } else {
                int l = o - 9;
                kr = lts + l * 33;
                qr = qns + row * 33;
                bias = lb[hh * 9 + l];
                slot = 73 + l;
            }
            float acc = bias;
#pragma unroll
            for (int d = 0; d < 32; d++) acc += qr[d] * kr[d];
            lg[row * 84 + slot] = acc;
        }
    }
    // S = Qs @ Kp^T (32x64x32, 3-term) on all 8 warps -> lg[..][0..63]
    {
        int mt = w >> 2, jp = w & 3;
        float sacc[2][4] = {};
#pragma unroll
        for (int kc = 0; kc < 2; kc++) {
            uint32_t qa[4], qb[4], kh4[4], kl4[4];
            uint32_t aoff = (uint32_t)((mt * 16 + (lane & 15)) * 40 +
                                       kc * 16 + (lane >> 4) * 8);
            ldsm_x4(qa, smem_u32(Qh + aoff));
            ldsm_x4(qb, smem_u32(Ql + aoff));
            int m = lane >> 3;
            uint32_t boff = (uint32_t)((jp * 16 + (m >> 1) * 8 + (lane & 7)) * 40 +
                                       kc * 16 + (m & 1) * 8);
            ldsm_x4(kh4, smem_u32(Kph + boff));
            ldsm_x4(kl4, smem_u32(Kpl + boff));
#pragma unroll
            for (int n8 = 0; n8 < 2; n8++) {
                mma_f16(sacc[n8], qa, kh4 + 2 * n8);
                mma_f16(sacc[n8], qb, kh4 + 2 * n8);
                mma_f16(sacc[n8], qa, kl4 + 2 * n8);
            }
        }
#pragma unroll
        for (int n8 = 0; n8 < 2; n8++)
#pragma unroll
            for (int hf = 0; hf < 2; hf++) {
                int row = mt * 16 + (lane >> 2) + hf * 8;
                int col = jp * 16 + n8 * 8 + (lane & 3) * 2;
                lg[row * 84 + col] = sacc[n8][hf * 2 + 0];
                lg[row * 84 + col + 1] = sacc[n8][hf * 2 + 1];
            }
    }
    __syncthreads();

    // softmax over 73 + local AV: 4 tokens/warp
#pragma unroll
    for (int tk = 0; tk < 4; tk++) {
        int row = w * 4 + tk;
        int n = ntile * 32 + row;
        int xl = n & 31;
        const int* rix = rel_idx + (size_t)n * 64;
        float s0 = lg[row * 84 + lane] + g_cpb[(size_t)rix[lane] * 8 + hh];
        float s1 = lg[row * 84 + 32 + lane] + g_cpb[(size_t)rix[lane + 32] * 8 + hh];
        float l0 = (lane < 9) ? lg[row * 84 + 64 + lane] : -3.4e38f;
        float mx = warp_max(fmaxf(fmaxf(s0, s1), l0));
        float e0 = expf(s0 - mx), e1 = expf(s1 - mx);
        float e2 = (lane < 9) ? expf(l0 - mx) : 0.f;
        float inv = 1.0f / warp_sum(e0 + e1 + e2);
        float p0 = e0 * inv, p1 = e1 * inv;
        __half p0h = __float2half_rn(p0);
        __half p1h = __float2half_rn(p1);
        Ph[row * 72 + lane] = p0h;
        Pl[row * 72 + lane] = __float2half_rn(p0 - __half2float(p0h));
        Ph[row * 72 + 32 + lane] = p1h;
        Pl[row * 72 + 32 + lane] = __float2half_rn(p1 - __half2float(p1h));
        if (lane < 9) lg[row * 84 + lane] = e2 * inv + lg[row * 84 + 73 + lane];
        __syncwarp();
        float outv = 0.f;
#pragma unroll
        for (int l = 0; l < 9; l++) {
            int r = l / 3, dc = l - r * 3;
            outv += lg[row * 84 + l] * Vw[(r * 34 + xl + dc) * 33 + lane];
        }
        lout[row * 33 + lane] = outv;
    }
    __syncthreads();

    // fused P @ Vp (32x32x64) on all 8 warps
    {
        const int mtile = w >> 2, j = w & 3;
        float acc[4] = {};
#pragma unroll
        for (int kc = 0; kc < 4; kc++) {
            uint32_t ph[4], pl[4], bv[2];
            uint32_t aoff = (uint32_t)((mtile * 16 + (lane & 15)) * 72 +
                                       kc * 16 + (lane >> 4) * 8);
            ldsm_x4(ph, smem_u32(Ph + aoff));
            ldsm_x4(pl, smem_u32(Pl + aoff));
            ldsm_x2(bv, smem_u32(Vt + ((lane & 7) + j * 8) * 72 +
                                 kc * 16 + ((lane >> 3) & 1) * 8));
            mma_f16(acc, ph, bv);
            mma_f16(acc, pl, bv);
        }
        const int d = j * 8 + (lane & 3) * 2;
#pragma unroll
        for (int hf = 0; hf < 2; hf++) {
            int wloc = mtile * 16 + (lane >> 2) + hf * 8;
            int nn = ntile * 32 + wloc;
            float lo0 = lout[wloc * 33 + d];
            float lo1 = lout[wloc * 33 + d + 1];
            float gt = g_gate[((size_t)(b * NTOK + nn)) * 8 + hh];
            float o0 = (acc[hf * 2 + 0] + lo0) * gt;
            float o1 = (acc[hf * 2 + 1] + lo1) * gt;
            *(__half2*)(g_ah + ((size_t)(b * NTOK + nn)) * CDIM + hh * HD + d) =
                __floats2half2_rn(o0, o1);
        }
    }
}

// ---------------- launch ----------------------------------------------------
extern "C" void kernel_launch(void* const* d_in, const int* in_sizes, int n_in,
                              void* d_out, int out_size) {
    const float* x      = (const float*)d_in[0];
    const float* rct    = (const float*)d_in[1];
    const float* q_w    = (const float*)d_in[2];
    const float* q_b    = (const float*)d_in[3];
    const float* kv_w   = (const float*)d_in[4];
    const float* kv_b   = (const float*)d_in[5];
    const float* temp   = (const float*)d_in[6];
    const float* qe     = (const float*)d_in[7];
    const float* rpb    = (const float*)d_in[8];
    const float* lt     = (const float*)d_in[9];
    const float* lb     = (const float*)d_in[10];
    const float* cpb1_w = (const float*)d_in[11];
    const float* cpb1_b = (const float*)d_in[12];
    const float* cpb2_w = (const float*)d_in[13];
    const float* cpb2_b = (const float*)d_in[14];
    const float* sr_w   = (const float*)d_in[15];
    const float* sr_b   = (const float*)d_in[16];
    const float* norm_g = (const float*)d_in[17];
    const float* norm_b = (const float*)d_in[18];
    const float* wg_w   = (const float*)d_in[19];
    const float* wg0_w  = (const float*)d_in[20];
    const float* wg1_w  = (const float*)d_in[21];
    const float* proj_w = (const float*)d_in[22];
    const float* proj_b = (const float*)d_in[23];
    const int*   ridx   = (const int*)d_in[24];
    float* out = (float*)d_out;

    float *pq, *pkv, *psr;
    __half *pxh, *pwh, *pwl, *pph, *pah;
    cudaGetSymbolAddress((void**)&pq,   g_q);
    cudaGetSymbolAddress((void**)&pkv,  g_kv);
    cudaGetSymbolAddress((void**)&psr,  g_sr);
    cudaGetSymbolAddress((void**)&pxh,  g_xh);
    cudaGetSymbolAddress((void**)&pwh,  g_wh);
    cudaGetSymbolAddress((void**)&pwl,  g_wl);
    cudaGetSymbolAddress((void**)&pph,  g_ph);
    cudaGetSymbolAddress((void**)&pah,  g_ah);

    cudaFuncSetAttribute(gemm_f16<0>,
                         cudaFuncAttributeMaxDynamicSharedMemorySize, GSMEM);
    cudaFuncSetAttribute(gemm_f16<1>,
                         cudaFuncAttributeMaxDynamicSharedMemorySize, GSMEM);
    cudaFuncSetAttribute(gemm_f16<2>,
                         cudaFuncAttributeMaxDynamicSharedMemorySize, GSMEM);
    cudaFuncSetAttribute(attn_soft,
                         cudaFuncAttributeMaxDynamicSharedMemorySize, ASMEMB);

    const int M = BATCH * NTOK;                       // 16384

    conv_x_gate<<<M / 8, 256>>>(x, wg_w, wg0_w, wg1_w);             // 0
    conv_w<<<320, 256>>>(q_w, kv_w, sr_w, proj_w);                  // 1
    cpb_kernel<<<TBLN, 128>>>(rct, cpb1_w, cpb1_b, cpb2_w, cpb2_b); // 2
    dim3 gf(8, M / 128);
    gemm_f16<0><<<gf, 256, GSMEM>>>(pxh, pwh, pwl,                  // 3 (profiled)
                                    pq, pkv, psr, q_b, kv_b, sr_b, 0,
                                    temp, qe);
    pool_ln<<<BATCH * PLP, 256>>>(norm_g, norm_b);                  // 4
    dim3 gp(4, 2);
    gemm_f16<2><<<gp, 256, GSMEM>>>(pph, pwh + 256 * 256, pwl + 256 * 256,
                                    nullptr, nullptr, nullptr, kv_b, nullptr,
                                    nullptr, 0, nullptr, nullptr);  // 5
    attn_soft<<<BATCH * NH * (NTOK / 32), 256, ASMEMB>>>(rpb, lt, lb, ridx); // 6
    dim3 gj(2, M / 128);
    gemm_f16<1><<<gj, 256, GSMEM>>>(pah, pwh + 1024 * 256, pwl + 1024 * 256,
                                    out, nullptr, nullptr, proj_b, nullptr,
                                    nullptr, 256, nullptr, nullptr); // 7
}

// round 16
// speedup vs baseline: 1.1267x; 1.1267x over previous
#include <cuda_runtime.h>
#include <cuda_bf16.h>
#include <cuda_fp16.h>
#include <math.h>
#include <stdint.h>

#define BATCH 4
#define NTOK  4096      // N = 64*64
#define CDIM  256
#define NH    8
#define HD    32
#define RESHW 64
#define PLP   64        // pooled length (8*8)
#define TBLN  4096
#define BH    (BATCH*NH)
#define EPSF  1.1920929e-07f

// ---------------- scratch (device globals; no dynamic alloc) ----------------
__device__ float g_q   [BATCH*NTOK*CDIM];        // q_norm fp32
__device__ float g_kv  [BATCH*NTOK*2*CDIM];      // kv; k half normalized
__device__ float g_gate[BATCH*NTOK*NH];
__device__ float g_cpb [TBLN*NH];
__device__ float g_spool[BH*NTOK*PLP];           // pool logits
__device__ __half g_srh[BATCH*NTOK*CDIM];        // gelu(sr) fp16
__device__ __half g_xh [BATCH*NTOK*CDIM];        // x fp16
__device__ __half g_wh [1280*CDIM];              // weights hi
__device__ __half g_wl [1280*CDIM];              // weights lo
__device__ __half g_ph [BATCH*PLP*CDIM];         // pooled+LN fp16
__device__ __half g_ah [BATCH*NTOK*CDIM];        // attention out fp16
__device__ __half g_qsh[BATCH*NTOK*CDIM];        // q_scaled hi
__device__ __half g_qsl[BATCH*NTOK*CDIM];        // q_scaled lo
__device__ __half g_kph[BATCH*PLP*CDIM];         // k_pool norm hi
__device__ __half g_kpl[BATCH*PLP*CDIM];         // k_pool norm lo
__device__ __half g_vph[BATCH*PLP*CDIM];         // v_pool fp16

__device__ __forceinline__ float warp_sum(float v) {
#pragma unroll
    for (int o = 16; o; o >>= 1) v += __shfl_xor_sync(0xffffffffu, v, o);
    return v;
}
__device__ __forceinline__ float warp_max(float v) {
#pragma unroll
    for (int o = 16; o; o >>= 1) v = fmaxf(v, __shfl_xor_sync(0xffffffffu, v, o));
    return v;
}

// ================= helpers ==================================================
__device__ __forceinline__ uint32_t smem_u32(const void* p) {
    uint32_t a;
    asm("{ .reg .u64 t; cvta.to.shared.u64 t, %1; cvt.u32.u64 %0, t; }"
        : "=r"(a) : "l"(p));
    return a;
}
__device__ __forceinline__ void ldsm_x4(uint32_t* r, uint32_t addr) {
    asm volatile("ldmatrix.sync.aligned.m8n8.x4.shared.b16 {%0,%1,%2,%3}, [%4];"
                 : "=r"(r[0]), "=r"(r[1]), "=r"(r[2]), "=r"(r[3]) : "r"(addr));
}
__device__ __forceinline__ void ldsm_x2(uint32_t* r, uint32_t addr) {
    asm volatile("ldmatrix.sync.aligned.m8n8.x2.shared.b16 {%0,%1}, [%2];"
                 : "=r"(r[0]), "=r"(r[1]) : "r"(addr));
}
__device__ __forceinline__ void mma_f16(float* c, const uint32_t* a,
                                        const uint32_t* b) {
    asm volatile(
        "mma.sync.aligned.m16n8k16.row.col.f32.f16.f16.f32 "
        "{%0,%1,%2,%3}, {%4,%5,%6,%7}, {%8,%9}, {%0,%1,%2,%3};"
        : "+f"(c[0]), "+f"(c[1]), "+f"(c[2]), "+f"(c[3])
        : "r"(a[0]), "r"(a[1]), "r"(a[2]), "r"(a[3]), "r"(b[0]), "r"(b[1]));
}
__device__ __forceinline__ void cp16(uint32_t dst, const void* src) {
    asm volatile("cp.async.cg.shared.global [%0], [%1], 16;"
                 :: "r"(dst), "l"(src));
}
#define CP_COMMIT() asm volatile("cp.async.commit_group;" ::: "memory")
#define CP_WAIT0()  asm volatile("cp.async.wait_group 0;" ::: "memory")
#define CP_WAIT1()  asm volatile("cp.async.wait_group 1;" ::: "memory")

// ================ merged prelude: x-convert+gating | w-convert | cpb =========
__global__ void __launch_bounds__(256)
prelude(const float* __restrict__ x, const float* __restrict__ wg,
        const float* __restrict__ wg0, const float* __restrict__ wg1,
        const float* __restrict__ qw, const float* __restrict__ kvw,
        const float* __restrict__ srw, const float* __restrict__ pjw,
        const float* __restrict__ tbl, const float* __restrict__ w1,
        const float* __restrict__ b1, const float* __restrict__ w2,
        const float* __restrict__ b2) {
    const int bid = blockIdx.x;
    const int tid = threadIdx.x;
    if (bid < 2048) {
        // ---- conv_x_gate ----
        int t = bid * 8 + (tid >> 5);
        int lane = tid & 31;
        const float* xt = x + (size_t)t * CDIM;
        float4 xa = *(const float4*)(xt + lane * 8);
        float4 xb = *(const float4*)(xt + lane * 8 + 4);
        __half2 h0 = __floats2half2_rn(xa.x, xa.y);
        __half2 h1 = __floats2half2_rn(xa.z, xa.w);
        __half2 h2 = __floats2half2_rn(xb.x, xb.y);
        __half2 h3 = __floats2half2_rn(xb.z, xb.w);
        uint4 u;
        u.x = *(uint32_t*)&h0; u.y = *(uint32_t*)&h1;
        u.z = *(uint32_t*)&h2; u.w = *(uint32_t*)&h3;
        *(uint4*)(g_xh + (size_t)t * CDIM + lane * 8) = u;
        float d[10];
#pragma unroll
        for (int i = 0; i < 10; i++) {
            const float* wr = (i < 4) ? wg + i * CDIM
                            : (i < 8) ? wg1 + (i - 4) * CDIM
                                      : wg0 + (i - 8) * CDIM;
            float4 wa = *(const float4*)(wr + lane * 8);
            float4 wb = *(const float4*)(wr + lane * 8 + 4);
            float s = xa.x * wa.x + xa.y * wa.y + xa.z * wa.z + xa.w * wa.w
                    + xb.x * wb.x + xb.y * wb.y + xb.z * wb.z + xb.w * wb.w;
            d[i] = warp_sum(s);
        }
        float m0 = fmaxf(fmaxf(d[0], d[1]), fmaxf(d[2], d[3]));
        float e[4], se = 0.f;
#pragma unroll
        for (int i = 0; i < 4; i++) { e[i] = expf(d[i] - m0); se += e[i]; }
        float gsm[4];
#pragma unroll
        for (int i = 0; i < 4; i++) gsm[i] = e[i] / se;
        int i1 = 0;
#pragma unroll
        for (int i = 1; i < 4; i++) if (gsm[i] > gsm[i1]) i1 = i;
        int i2 = -1;
#pragma unroll
        for (int i = 0; i < 4; i++) {
            if (i == i1) continue;
            if (i2 < 0 || gsm[i] > gsm[i2]) i2 = i;
        }
        float rs = fmaxf(gsm[i1] + gsm[i2], EPSF);
        float routed[4];
#pragma unroll
        for (int i = 0; i < 4; i++)
            routed[i] = (i == i1 || i == i2) ? gsm[i] / rs * 2.f : 0.f;
        float m1 = fmaxf(fmaxf(d[4], d[5]), fmaxf(d[6], d[7]));
        float es[4], ss = 0.f;
#pragma unroll
        for (int i = 0; i < 4; i++) { es[i] = expf(d[4 + i] - m1); ss += es[i]; }
        float shg[4];
#pragma unroll
        for (int i = 0; i < 4; i++) shg[i] = es[i] / ss * 4.f;
        float m2 = fmaxf(d[8], d[9]);
        float e8 = expf(d[8] - m2), e9 = expf(d[9] - m2);
        float w00 = e8 / (e8 + e9) * 2.f;
        float w01 = e9 / (e8 + e9) * 2.f;
        if (lane < NH) {
            float v = (lane < 4) ? w00 * shg[lane] : w01 * routed[lane - 4];
            g_gate[(size_t)t * NH + lane] = v;
        }
    } else if (bid < 2368) {
        // ---- conv_w ----
        int i = (bid - 2048) * 256 + tid;   // float4 index
        int row = i >> 6;
        const float4* src;
        int off;
        if (row < 256)       { src = (const float4*)qw;  off = i; }
        else if (row < 768)  { src = (const float4*)kvw; off = i - 256 * 64; }
        else if (row < 1024) { src = (const float4*)srw; off = i - 768 * 64; }
        else                 { src = (const float4*)pjw; off = i - 1024 * 64; }
        float4 v = src[off];
        __half a0 = __float2half_rn(v.x), a1 = __float2half_rn(v.y);
        __half a2 = __float2half_rn(v.z), a3 = __float2half_rn(v.w);
        __half c0 = __float2half_rn(v.x - __half2float(a0));
        __half c1 = __float2half_rn(v.y - __half2float(a1));
        __half c2 = __float2half_rn(v.z - __half2float(a2));
        __half c3 = __float2half_rn(v.w - __half2float(a3));
        ushort4 H, L;
        H.x = *(uint16_t*)&a0; H.y = *(uint16_t*)&a1;
        H.z = *(uint16_t*)&a2; H.w = *(uint16_t*)&a3;
        L.x = *(uint16_t*)&c0; L.y = *(uint16_t*)&c1;
        L.z = *(uint16_t*)&c2; L.w = *(uint16_t*)&c3;
        ((ushort4*)g_wh)[i] = H;
        ((ushort4*)g_wl)[i] = L;
    } else {
        // ---- cpb: 2 table rows per block ----
        int sub = tid >> 7, t = tid & 127;
        int row = (bid - 2368) * 2 + sub;
        float t0 = tbl[row * 2 + 0], t1 = tbl[row * 2 + 1];
        float acc[8] = {};
        for (int j = t; j < 512; j += 128) {
            float hv = fmaxf(t0 * w1[2 * j] + t1 * w1[2 * j + 1] + b1[j], 0.f);
#pragma unroll
            for (int o = 0; o < 8; o++) acc[o] += hv * w2[o * 512 + j];
        }
#pragma unroll
        for (int o = 0; o < 8; o++) acc[o] = warp_sum(acc[o]);
        __shared__ float sh2[2][4][8];
        int wp = t >> 5, lane = t & 31;
        if (lane == 0)
#pragma unroll
            for (int o = 0; o < 8; o++) sh2[sub][wp][o] = acc[o];
        __syncthreads();
        if (t < 8)
            g_cpb[(size_t)row * 8 + t] =
                sh2[sub][0][t] + sh2[sub][1][t] + sh2[sub][2][t] +
                sh2[sub][3][t] + b2[t];
    }
}

// ================= 3-stage pipelined 2-term fp16 GEMM =======================
// MODE 0: fused q/kv/sr + q/k L2 norm epilogue.  MODE 1: plain.  MODE 2: pooled
// kv epilogue (normalize k per head -> kph/kpl fp16, v -> vph fp16).
#define MATSZ (128 * 40)
#define STAGEB (3 * MATSZ * 2)
#define GSMEM (3 * STAGEB)          // 92160 B

template<int MODE>
__global__ void __launch_bounds__(256, 2)
gemm_f16(const __half* __restrict__ A,
         const __half* __restrict__ Wh, const __half* __restrict__ Wl,
         float* __restrict__ C0,
         const float* __restrict__ b0, const float* __restrict__ b1,
         const float* __restrict__ b2, int ldc0,
         const float* __restrict__ temp, const float* __restrict__ qe) {
    extern __shared__ uint16_t sd[];
    const int bm = blockIdx.y * 128, bn = blockIdx.x * 128;
    const int tid = threadIdx.x, lane = tid & 31, wid = tid >> 5;
    const int wm = (wid & 3) * 32, wn = (wid >> 2) * 64;
    float acc[2][8][4] = {};

    const __half* gsrc[3] = {
        A + (size_t)bm * 256, Wh + (size_t)bn * 256, Wl + (size_t)bn * 256};

    const int ldrow = tid >> 2, ldpart = tid & 3;
    const uint32_t sb0 = smem_u32(sd);
    uint32_t aAdr[2];
#pragma unroll
    for (int i = 0; i < 2; i++)
        aAdr[i] = sb0 + 2 * ((wm + i * 16 + (lane & 15)) * 40 + (lane >> 4) * 8);
    uint32_t bAdr[4];
    {
        int m = lane >> 3;
#pragma unroll
        for (int jp = 0; jp < 4; jp++)
            bAdr[jp] = sb0 + 2 * (MATSZ + (wn + jp * 16 + (m >> 1) * 8 +
                                           (lane & 7)) * 40 + (m & 1) * 8);
    }

#define GLOAD(stage, ko) do {                                                  \
    const int nb_ = (stage) * 3 * MATSZ;                                       \
    _Pragma("unroll")                                                          \
    for (int m_ = 0; m_ < 3; m_++)                                             \
        _Pragma("unroll")                                                      \
        for (int s_ = 0; s_ < 2; s_++) {                                       \
            int row_ = ldrow + s_ * 64;                                        \
            cp16(smem_u32(sd + nb_ + m_ * MATSZ + row_ * 40 + ldpart * 8),     \
                 gsrc[m_] + (size_t)row_ * 256 + (ko) + ldpart * 8);           \
        }                                                                      \
    CP_COMMIT();                                                               \
} while (0)

    GLOAD(0, 0);
    GLOAD(1, 32);

#pragma unroll
    for (int kc = 0; kc < 8; kc++) {
        const int stg = kc % 3;
        const uint32_t so = (uint32_t)stg * STAGEB;
        if (kc < 7) { CP_WAIT1(); } else { CP_WAIT0(); }
        __syncthreads();
        if (kc < 6) GLOAD((kc + 2) % 3, (kc + 2) * 32);
#pragma unroll
        for (int ks = 0; ks < 2; ks++) {
            const uint32_t so2 = so + ks * 32;
            uint32_t ah[2][4];
            ldsm_x4(ah[0], aAdr[0] + so2);
            ldsm_x4(ah[1], aAdr[1] + so2);
#pragma unroll
            for (int jp = 0; jp < 4; jp++) {
                uint32_t bh[4], bl[4];
                ldsm_x4(bh, bAdr[jp] + so2);
                ldsm_x4(bl, bAdr[jp] + so2 + 2 * MATSZ);
#pragma unroll
                for (int i = 0; i < 2; i++) {
                    mma_f16(acc[i][jp * 2], ah[i], bh);
                    mma_f16(acc[i][jp * 2], ah[i], bl);
                    mma_f16(acc[i][jp * 2 + 1], ah[i], bh + 2);
                    mma_f16(acc[i][jp * 2 + 1], ah[i], bl + 2);
                }
            }
        }
    }
#undef GLOAD

    if (MODE == 0) {
        const int r = bn >> 7;
        const bool isQ = r < 2, isK = (r == 2 || r == 3), isSR = r >= 6;
        const float* bias = isQ ? b0 : (r < 6 ? b1 : b2);
        const int cb = isQ ? bn : (r < 6 ? bn - 256 : bn - 768);
#pragma unroll
        for (int i = 0; i < 2; i++)
#pragma unroll
            for (int j = 0; j < 8; j++) {
                int col = cb + wn + j * 8 + (lane & 3) * 2;
                float bb0 = bias[col], bb1 = bias[col + 1];
                acc[i][j][0] += bb0; acc[i][j][1] += bb1;
                acc[i][j][2] += bb0; acc[i][j][3] += bb1;
                if (isSR) {
#pragma unroll
                    for (int t = 0; t < 4; t++) {
                        float v = acc[i][j][t];
                        acc[i][j][t] =
                            0.5f * v * (1.0f + erff(v * 0.70710678118654752f));
                    }
                }
            }
        if (isQ || isK) {
            float* sums = (float*)sd;
            sums[tid] = 0.f; sums[tid + 256] = 0.f;
            __syncthreads();
#pragma unroll
            for (int i = 0; i < 2; i++)
#pragma unroll
                for (int half = 0; half < 2; half++)
#pragma unroll
                    for (int hg = 0; hg < 2; hg++) {
                        float p = 0.f;
#pragma unroll
                        for (int j = hg * 4; j < hg * 4 + 4; j++)
                            p += acc[i][j][half * 2] * acc[i][j][half * 2] +
                                 acc[i][j][half * 2 + 1] * acc[i][j][half * 2 + 1];
                        p += __shfl_xor_sync(0xffffffffu, p, 1);
                        p += __shfl_xor_sync(0xffffffffu, p, 2);
                        if ((lane & 3) == 0) {
                            int rr = wm + i * 16 + (lane >> 2) + half * 8;
                            atomicAdd(&sums[rr * 4 + (wn >> 5) + hg], p);
                        }
                    }
            __syncthreads();
            if (isQ) {
                float sp[2];
#pragma unroll
                for (int hg = 0; hg < 2; hg++)
                    sp[hg] = log1pf(expf(temp[((bn + wn) >> 5) + hg]));
                float sls[2][2];
#pragma unroll
                for (int i = 0; i < 2; i++)
#pragma unroll
                    for (int half = 0; half < 2; half++) {
                        int row = wm + i * 16 + (lane >> 2) + half * 8;
                        int n = (bm + row) & (NTOK - 1);
                        int yq = n >> 6, xq = n & 63;
                        int chh = min(yq + 1, 63) - max(yq - 1, 0) + 1;
                        int cww = min(xq + 1, 63) - max(xq - 1, 0) + 1;
                        sls[i][half] = logf((float)(chh * cww + PLP));
                    }
#pragma unroll
                for (int i = 0; i < 2; i++)
#pragma unroll
                    for (int j = 0; j < 8; j++) {
                        int hg = j >> 2;
                        int gcol = bn + wn + j * 8 + (lane & 3) * 2;
                        float qe0 = qe[gcol];
                        float qe1 = qe[gcol + 1];
#pragma unroll
                        for (int half = 0; half < 2; half++) {
                            int row = wm + i * 16 + (lane >> 2) + half * 8;
                            float inv = 1.f /
                                fmaxf(sqrtf(sums[row * 4 + (wn >> 5) + hg]), EPSF);
                            float q0 = acc[i][j][half * 2] * inv;
                            float q1 = acc[i][j][half * 2 + 1] * inv;
                            size_t go = (size_t)(bm + row) * 256 + gcol;
                            float2 f2; f2.x = q0; f2.y = q1;
                            *(float2*)(g_q + go) = f2;
                            float m = sp[hg] * sls[i][half];
                            float s0 = (q0 + qe0) * m, s1 = (q1 + qe1) * m;
                            __half hh0 = __float2half_rn(s0);
                            __half hh1 = __float2half_rn(s1);
                            *(__half2*)(g_qsh + go) = __halves2half2(hh0, hh1);
                            *(__half2*)(g_qsl + go) = __halves2half2(
                                __float2half_rn(s0 - __half2float(hh0)),
                                __float2half_rn(s1 - __half2float(hh1)));
                        }
                    }
            } else {
#pragma unroll
                for (int i = 0; i < 2; i++)
#pragma unroll
                    for (int j = 0; j < 8; j++) {
                        int hg = j >> 2;
                        int gcol = cb + wn + j * 8 + (lane & 3) * 2;
#pragma unroll
                        for (int half = 0; half < 2; half++) {
                            int row = wm + i * 16 + (lane >> 2) + half * 8;
                            float inv = 1.f /
                                fmaxf(sqrtf(sums[row * 4 + (wn >> 5) + hg]), EPSF);
                            float2 f2;
                            f2.x = acc[i][j][half * 2] * inv;
                            f2.y = acc[i][j][half * 2 + 1] * inv;
                            *(float2*)(g_kv + (size_t)(bm + row) * 512 + gcol) = f2;
                        }
                    }
            }
        } else if (isSR) {
            // store gelu(sr) as fp16
#pragma unroll
            for (int i = 0; i < 2; i++) {
                int r0 = bm + wm + i * 16 + (lane >> 2);
#pragma unroll
                for (int j = 0; j < 8; j++) {
                    int col = cb + wn + j * 8 + (lane & 3) * 2;
                    *(__half2*)(g_srh + (size_t)r0 * 256 + col) =
                        __floats2half2_rn(acc[i][j][0], acc[i][j][1]);
                    *(__half2*)(g_srh + (size_t)(r0 + 8) * 256 + col) =
                        __floats2half2_rn(acc[i][j][2], acc[i][j][3]);
                }
            }
        } else {
            // v tiles: plain fp32 store into g_kv second half
#pragma unroll
            for (int i = 0; i < 2; i++) {
                int r0 = bm + wm + i * 16 + (lane >> 2);
#pragma unroll
                for (int j = 0; j < 8; j++) {
                    int col = cb + wn + j * 8 + (lane & 3) * 2;
                    float2 o01; o01.x = acc[i][j][0]; o01.y = acc[i][j][1];
                    float2 o23; o23.x = acc[i][j][2]; o23.y = acc[i][j][3];
                    *(float2*)(g_kv + (size_t)r0 * 512 + col) = o01;
                    *(float2*)(g_kv + (size_t)(r0 + 8) * 512 + col) = o23;
                }
            }
        }
        return;
    }
    if (MODE == 2) {
        const bool isKp = bn < 256;
#pragma unroll
        for (int i = 0; i < 2; i++)
#pragma unroll
            for (int j = 0; j < 8; j++) {
                int col = bn + wn + j * 8 + (lane & 3) * 2;
                float bb0 = b0[col], bb1 = b0[col + 1];
                acc[i][j][0] += bb0; acc[i][j][1] += bb1;
                acc[i][j][2] += bb0; acc[i][j][3] += bb1;
            }
        if (isKp) {
            float* sums = (float*)sd;
            sums[tid] = 0.f; sums[tid + 256] = 0.f;
            __syncthreads();
#pragma unroll
            for (int i = 0; i < 2; i++)
#pragma unroll
                for (int half = 0; half < 2; half++)
#pragma unroll
                    for (int hg = 0; hg < 2; hg++) {
                        float p = 0.f;
#pragma unroll
                        for (int j = hg * 4; j < hg * 4 + 4; j++)
                            p += acc[i][j][half * 2] * acc[i][j][half * 2] +
                                 acc[i][j][half * 2 + 1] * acc[i][j][half * 2 + 1];
                        p += __shfl_xor_sync(0xffffffffu, p, 1);
                        p += __shfl_xor_sync(0xffffffffu, p, 2);
                        if ((lane & 3) == 0) {
                            int rr = wm + i * 16 + (lane >> 2) + half * 8;
                            atomicAdd(&sums[rr * 4 + (wn >> 5) + hg], p);
                        }
                    }
            __syncthreads();
#pragma unroll
            for (int i = 0; i < 2; i++)
#pragma unroll
                for (int j = 0; j < 8; j++) {
                    int hg = j >> 2;
                    int gcol = bn + wn + j * 8 + (lane & 3) * 2;
#pragma unroll
                    for (int half = 0; half < 2; half++) {
                        int row = wm + i * 16 + (lane >> 2) + half * 8;
                        float inv = 1.f /
                            fmaxf(sqrtf(sums[row * 4 + (wn >> 5) + hg]), EPSF);
                        float k0 = acc[i][j][half * 2] * inv;
                        float k1 = acc[i][j][half * 2 + 1] * inv;
                        __half hh0 = __float2half_rn(k0);
                        __half hh1 = __float2half_rn(k1);
                        size_t go = (size_t)(bm + row) * 256 + gcol;
                        *(__half2*)(g_kph + go) = __halves2half2(hh0, hh1);
                        *(__half2*)(g_kpl + go) = __halves2half2(
                            __float2half_rn(k0 - __half2float(hh0)),
                            __float2half_rn(k1 - __half2float(hh1)));
                    }
                }
        } else {
#pragma unroll
            for (int i = 0; i < 2; i++)
#pragma unroll
                for (int j = 0; j < 8; j++) {
                    int gcol = bn - 256 + wn + j * 8 + (lane & 3) * 2;
#pragma unroll
                    for (int half = 0; half < 2; half++) {
                        int row = wm + i * 16 + (lane >> 2) + half * 8;
                        *(__half2*)(g_vph + (size_t)(bm + row) * 256 + gcol) =
                            __floats2half2_rn(acc[i][j][half * 2],
                                              acc[i][j][half * 2 + 1]);
                    }
                }
        }
        return;
    }
    // MODE 1
#pragma unroll
    for (int i = 0; i < 2; i++) {
        int r0 = bm + wm + i * 16 + (lane >> 2);
#pragma unroll
        for (int j = 0; j < 8; j++) {
            int col = bn + wn + j * 8 + (lane & 3) * 2;
            float bb0 = b0[col], bb1 = b0[col + 1];
            float2 o01; o01.x = acc[i][j][0] + bb0; o01.y = acc[i][j][1] + bb1;
            float2 o23; o23.x = acc[i][j][2] + bb0; o23.y = acc[i][j][3] + bb1;
            *(float2*)(C0 + (size_t)r0 * ldc0 + col) = o01;
            *(float2*)(C0 + (size_t)(r0 + 8) * ldc0 + col) = o23;
        }
    }
}

// ---------------- 8x8 avg pool + LayerNorm (fp16 in, fp16 out) ---------------
__global__ void __launch_bounds__(256)
pool_ln(const float* __restrict__ gw, const float* __restrict__ gb) {
    int bp = blockIdx.x;
    int b = bp >> 6, p = bp & 63;
    int py = p >> 3, px = p & 7;
    int c = threadIdx.x;
    const __half* base = g_srh + (size_t)b * NTOK * CDIM;
    float s = 0.f;
    for (int iy = 0; iy < 8; iy++) {
        int y = py * 8 + iy;
        for (int ix = 0; ix < 8; ix++) {
            int n = y * RESHW + px * 8 + ix;
            s += __half2float(base[(size_t)n * CDIM + c]);
        }
    }
    float val = s * (1.0f / 64.0f);
    __shared__ float red[256];
    red[c] = val; __syncthreads();
    for (int st = 128; st > 0; st >>= 1) { if (c < st) red[c] += red[c + st]; __syncthreads(); }
    float mu = red[0] * (1.0f / 256.0f);
    __syncthreads();
    float dv = val - mu;
    red[c] = dv * dv; __syncthreads();
    for (int st = 128; st > 0; st >>= 1) { if (c < st) red[c] += red[c + st]; __syncthreads(); }
    float var = red[0] * (1.0f / 256.0f);
    float ov = dv * rsqrtf(var + 1e-5f) * gw[c] + gb[c];
    g_ph[(size_t)bp * CDIM + c] = __float2half_rn(ov);
}

// ================ pool logits via mma (S = Qs @ Kp^T, 3-term) ================
__global__ void __launch_bounds__(256)
pool_logits() {
    __shared__ __align__(16) uint16_t sQh[128 * 40];
    __shared__ __align__(16) uint16_t sQl[128 * 40];
    __shared__ __align__(16) uint16_t sKh[64 * 40];
    __shared__ __align__(16) uint16_t sKl[64 * 40];
    const int mtile = blockIdx.x, bh = blockIdx.y;
    const int b = bh >> 3, h = bh & 7;
    const int tid = threadIdx.x, lane = tid & 31, wid = tid >> 5;
    const int wm = wid * 16;
    const int n0 = mtile * 128;
    for (int i = tid; i < 512; i += 256) {
        int row = i >> 2, part = i & 3;
        size_t src = ((size_t)(b * NTOK + n0 + row)) * CDIM + h * HD + part * 8;
        cp16(smem_u32(sQh + row * 40 + part * 8), g_qsh + src);
        cp16(smem_u32(sQl + row * 40 + part * 8), g_qsl + src);
    }
    {
        int i = tid;
        if (i < 256) {
            int row = i >> 2, part = i & 3;
            size_t src = ((size_t)(b * PLP + row)) * CDIM + h * HD + part * 8;
            cp16(smem_u32(sKh + row * 40 + part * 8), g_kph + src);
            cp16(smem_u32(sKl + row * 40 + part * 8), g_kpl + src);
        }
    }
    CP_COMMIT(); CP_WAIT0();
    __syncthreads();
    float acc[8][4] = {};
#pragma unroll
    for (int ks = 0; ks < 2; ks++) {
        uint32_t qh[4], ql[4];
        const int arow = lane & 15, acol = ks * 16 + (lane >> 4) * 8;
        ldsm_x4(qh, smem_u32(sQh + (wm + arow) * 40 + acol));
        ldsm_x4(ql, smem_u32(sQl + (wm + arow) * 40 + acol));
        const int brow0 = lane & 7;
        const int bcol = ks * 16 + ((lane >> 3) & 1) * 8;
#pragma unroll
        for (int j = 0; j < 8; j++) {
            uint32_t kh[2], kl[2];
            ldsm_x2(kh, smem_u32(sKh + (brow0 + j * 8) * 40 + bcol));
            ldsm_x2(kl, smem_u32(sKl + (brow0 + j * 8) * 40 + bcol));
            mma_f16(acc[j], qh, kh);
            mma_f16(acc[j], ql, kh);
            mma_f16(acc[j], qh, kl);
        }
    }
    int r0 = n0 + wm + (lane >> 2);
#pragma unroll
    for (int j = 0; j < 8; j++) {
        int col = j * 8 + (lane & 3) * 2;
        float2 a; a.x = acc[j][0]; a.y = acc[j][1];
        float2 c; c.x = acc[j][2]; c.y = acc[j][3];
        *(float2*)(g_spool + ((size_t)bh * NTOK + r0) * PLP + col) = a;
        *(float2*)(g_spool + ((size_t)bh * NTOK + r0 + 8) * PLP + col) = c;
    }
}

// ================ attn: local logits + softmax + local AV + fused P@Vp =======
#define AKW 0
#define AVW 3366
#define AQS 6732
#define AQN 7788
#define ALG 8844
#define ALT 11532
#define ALO 11832
#define AFLOATS 12888
#define ASMEMB (AFLOATS * 4 + 3 * 2304 * 2)   // 65376 B

__global__ void __launch_bounds__(1024)
attn_soft(const float* __restrict__ rpb, const float* __restrict__ lt,
          const float* __restrict__ lb, const int* __restrict__ rel_idx) {
    extern __shared__ float sh[];
    float* Kw  = sh + AKW;     // [102][33]
    float* Vw  = sh + AVW;
    float* qss = sh + AQS;     // [32][33]
    float* qns = sh + AQN;
    float* lg  = sh + ALG;     // [32][84]
    float* lts = sh + ALT;     // [9][33]
    float* lout = sh + ALO;    // [32][33]
    __half* Ph = (__half*)(sh + AFLOATS);   // [32][72]
    __half* Pl = Ph + 2304;
    __half* Vt = Pl + 2304;                 // [32][72] (d-major)
    int blk = blockIdx.x;
    int ntile = blk & 127;
    int hh = (blk >> 7) & 7;
    int b = blk >> 10;
    int bh = b * 8 + hh;
    int tid = threadIdx.x, w = tid >> 5, lane = tid & 31;
    int y = ntile >> 1, x0 = (ntile & 1) << 5;

    for (int i = tid; i < 3264; i += 1024) {
        int vec = i >> 5, d = i & 31;
        int r = vec / 34, c = vec - r * 34;
        int yy = y + r - 1, xx = x0 - 1 + c;
        float kv0 = 0.f, vv0 = 0.f;
        if ((unsigned)yy < 64u && (unsigned)xx < 64u) {
            size_t base = ((size_t)(b * NTOK + yy * 64 + xx)) * 512 + hh * 32 + d;
            kv0 = g_kv[base];
            vv0 = g_kv[base + 256];
        }
        Kw[vec * 33 + d] = kv0;
        Vw[vec * 33 + d] = vv0;
    }
    if (tid < 288) {
        int d = tid / 9, l = tid - d * 9;
        lts[l * 33 + d] = lt[hh * 288 + tid];
    }
    for (int i = tid; i < 2048; i += 1024) {
        int p = i >> 5, d = i & 31;
        Vt[d * 72 + p] =
            g_vph[((size_t)(b * PLP + p)) * CDIM + hh * HD + d];
    }
    int n = ntile * 32 + w;
    size_t qoff = ((size_t)(b * NTOK + n)) * 256 + hh * 32 + lane;
    qss[w * 33 + lane] = __half2float(g_qsh[qoff]) + __half2float(g_qsl[qoff]);
    qns[w * 33 + lane] = g_q[qoff];
    __syncthreads();

    int xl = n & 31;
    const int* rix = rel_idx + (size_t)n * 64;
    {
        int o = lane;
        if (o < 18) {
            const float* kr;
            const float* qr;
            float bias;
            int slot;
            if (o < 9) {
                int r = o / 3, dc = o - r * 3;
                kr = Kw + (r * 34 + xl + dc) * 33;
                qr = qss + w * 33;
                bias = rpb[hh * 9 + o];
                slot = 64 + o;
            } else {
                int l = o - 9;
                kr = lts + l * 33;
                qr = qns + w * 33;
                bias = lb[hh * 9 + l];
                slot = 73 + l;
            }
            float acc = bias;
#pragma unroll
            for (int d = 0; d < 32; d++) acc += qr[d] * kr[d];
            lg[w * 84 + slot] = acc;
        }
    }
    __syncwarp();
    size_t soff = ((size_t)bh * NTOK + n) * 64;
    float s0 = g_spool[soff + lane] + g_cpb[(size_t)rix[lane] * 8 + hh];
    float s1 = g_spool[soff + 32 + lane] + g_cpb[(size_t)rix[lane + 32] * 8 + hh];
    float l0 = (lane < 9) ? lg[w * 84 + 64 + lane] : -3.4e38f;
    float mx = warp_max(fmaxf(fmaxf(s0, s1), l0));
    float e0 = expf(s0 - mx), e1 = expf(s1 - mx);
    float e2 = (lane < 9) ? expf(l0 - mx) : 0.f;
    float inv = 1.0f / warp_sum(e0 + e1 + e2);
    float p0 = e0 * inv, p1 = e1 * inv;
    __half p0h = __float2half_rn(p0);
    __half p1h = __float2half_rn(p1);
    Ph[w * 72 + lane] = p0h;
    Pl[w * 72 + lane] = __float2half_rn(p0 - __half2float(p0h));
    Ph[w * 72 + 32 + lane] = p1h;
    Pl[w * 72 + 32 + lane] = __float2half_rn(p1 - __half2float(p1h));
    if (lane < 9) lg[w * 84 + lane] = e2 * inv + lg[w * 84 + 73 + lane];
    __syncwarp();
    float outv = 0.f;
#pragma unroll
    for (int l = 0; l < 9; l++) {
        int r = l / 3, dc = l - r * 3;
        outv += lg[w * 84 + l] * Vw[(r * 34 + xl + dc) * 33 + lane];
    }
    lout[w * 33 + lane] = outv;
    __syncthreads();

    if (w < 8) {
        const int mtile = w >> 2, j = w & 3;
        float acc[4] = {};
#pragma unroll
        for (int kc = 0; kc < 4; kc++) {
            uint32_t ph[4], pl[4], bv[2];
            uint32_t aoff = (uint32_t)((mtile * 16 + (lane & 15)) * 72 +
                                       kc * 16 + (lane >> 4) * 8);
            ldsm_x4(ph, smem_u32(Ph + aoff));
            ldsm_x4(pl, smem_u32(Pl + aoff));
            ldsm_x2(bv, smem_u32(Vt + ((lane & 7) + j * 8) * 72 +
                                 kc * 16 + ((lane >> 3) & 1) * 8));
            mma_f16(acc, ph, bv);
            mma_f16(acc, pl, bv);
        }
        const int d = j * 8 + (lane & 3) * 2;
#pragma unroll
        for (int hf = 0; hf < 2; hf++) {
            int wloc = mtile * 16 + (lane >> 2) + hf * 8;
            int nn = ntile * 32 + wloc;
            float lo0 = lout[wloc * 33 + d];
            float lo1 = lout[wloc * 33 + d + 1];
            float gt = g_gate[((size_t)(b * NTOK + nn)) * 8 + hh];
            float o0 = (acc[hf * 2 + 0] + lo0) * gt;
            float o1 = (acc[hf * 2 + 1] + lo1) * gt;
            *(__half2*)(g_ah + ((size_t)(b * NTOK + nn)) * CDIM + hh * HD + d) =
                __floats2half2_rn(o0, o1);
        }
    }
}

// ---------------- launch ----------------------------------------------------
extern "C" void kernel_launch(void* const* d_in, const int* in_sizes, int n_in,
                              void* d_out, int out_size) {
    const float* x      = (const float*)d_in[0];
    const float* rct    = (const float*)d_in[1];
    const float* q_w    = (const float*)d_in[2];
    const float* q_b    = (const float*)d_in[3];
    const float* kv_w   = (const float*)d_in[4];
    const float* kv_b   = (const float*)d_in[5];
    const float* temp   = (const float*)d_in[6];
    const float* qe     = (const float*)d_in[7];
    const float* rpb    = (const float*)d_in[8];
    const float* lt     = (const float*)d_in[9];
    const float* lb     = (const float*)d_in[10];
    const float* cpb1_w = (const float*)d_in[11];
    const float* cpb1_b = (const float*)d_in[12];
    const float* cpb2_w = (const float*)d_in[13];
    const float* cpb2_b = (const float*)d_in[14];
    const float* sr_w   = (const float*)d_in[15];
    const float* sr_b   = (const float*)d_in[16];
    const float* norm_g = (const float*)d_in[17];
    const float* norm_b = (const float*)d_in[18];
    const float* wg_w   = (const float*)d_in[19];
    const float* wg0_w  = (const float*)d_in[20];
    const float* wg1_w  = (const float*)d_in[21];
    const float* proj_w = (const float*)d_in[22];
    const float* proj_b = (const float*)d_in[23];
    const int*   ridx   = (const int*)d_in[24];
    float* out = (float*)d_out;

    __half *pxh, *pwh, *pwl, *pph, *pah;
    cudaGetSymbolAddress((void**)&pxh,  g_xh);
    cudaGetSymbolAddress((void**)&pwh,  g_wh);
    cudaGetSymbolAddress((void**)&pwl,  g_wl);
    cudaGetSymbolAddress((void**)&pph,  g_ph);
    cudaGetSymbolAddress((void**)&pah,  g_ah);

    cudaFuncSetAttribute(gemm_f16<0>,
                         cudaFuncAttributeMaxDynamicSharedMemorySize, GSMEM);
    cudaFuncSetAttribute(gemm_f16<1>,
                         cudaFuncAttributeMaxDynamicSharedMemorySize, GSMEM);
    cudaFuncSetAttribute(gemm_f16<2>,
                         cudaFuncAttributeMaxDynamicSharedMemorySize, GSMEM);
    cudaFuncSetAttribute(attn_soft,
                         cudaFuncAttributeMaxDynamicSharedMemorySize, ASMEMB);

    const int M = BATCH * NTOK;                       // 16384

    prelude<<<4416, 256>>>(x, wg_w, wg0_w, wg1_w, q_w, kv_w, sr_w, proj_w,
                           rct, cpb1_w, cpb1_b, cpb2_w, cpb2_b);    // 0
    dim3 gf(8, M / 128);
    gemm_f16<0><<<gf, 256, GSMEM>>>(pxh, pwh, pwl, nullptr,         // 1
                                    q_b, kv_b, sr_b, 0, temp, qe);
    pool_ln<<<BATCH * PLP, 256>>>(norm_g, norm_b);                  // 2
    dim3 gp(4, 2);
    gemm_f16<2><<<gp, 256, GSMEM>>>(pph, pwh + 256 * 256, pwl + 256 * 256,
                                    nullptr, kv_b, nullptr, nullptr, 0,
                                    nullptr, nullptr);              // 3
    dim3 ga(NTOK / 128, BH);
    pool_logits<<<ga, 256>>>();                                     // 4
    attn_soft<<<BATCH * NH * (NTOK / 32), 1024, ASMEMB>>>(rpb, lt, lb, ridx); // 5
    dim3 gj(2, M / 128);
    gemm_f16<1><<<gj, 256, GSMEM>>>(pah, pwh + 1024 * 256, pwl + 1024 * 256,
                                    out, proj_b, nullptr, nullptr, 256,
                                    nullptr, nullptr);              // 6
}

// round 17
// speedup vs baseline: 1.1368x; 1.0090x over previous
#include <cuda_runtime.h>
#include <cuda_bf16.h>
#include <cuda_fp16.h>
#include <math.h>
#include <stdint.h>

#define BATCH 4
#define NTOK  4096      // N = 64*64
#define CDIM  256
#define NH    8
#define HD    32
#define RESHW 64
#define PLP   64        // pooled length (8*8)
#define TBLN  4096
#define BH    (BATCH*NH)
#define EPSF  1.1920929e-07f

// ---------------- scratch (device globals; no dynamic alloc) ----------------
__device__ float g_q   [BATCH*NTOK*CDIM];        // q_norm fp32
__device__ float g_kv  [BATCH*NTOK*2*CDIM];      // kv; k half normalized
__device__ float g_gate[BATCH*NTOK*NH];
__device__ float g_cpb [TBLN*NH];
__device__ float g_spool[BH*NTOK*PLP];           // pool logits
__device__ __half g_srh[BATCH*NTOK*CDIM];        // gelu(sr) fp16
__device__ __half g_xh [BATCH*NTOK*CDIM];        // x fp16
__device__ __half g_wh [1280*CDIM];              // weights hi
__device__ __half g_wl [1280*CDIM];              // weights lo
__device__ __half g_ph [BATCH*PLP*CDIM];         // pooled+LN fp16
__device__ __half g_ah [BATCH*NTOK*CDIM];        // attention out fp16
__device__ __half g_qsh[BATCH*NTOK*CDIM];        // q_scaled hi
__device__ __half g_qsl[BATCH*NTOK*CDIM];        // q_scaled lo
__device__ __half g_kph[BATCH*PLP*CDIM];         // k_pool norm hi
__device__ __half g_kpl[BATCH*PLP*CDIM];         // k_pool norm lo
__device__ __half g_vph[BATCH*PLP*CDIM];         // v_pool fp16

__device__ __forceinline__ float warp_sum(float v) {
#pragma unroll
    for (int o = 16; o; o >>= 1) v += __shfl_xor_sync(0xffffffffu, v, o);
    return v;
}
__device__ __forceinline__ float warp_max(float v) {
#pragma unroll
    for (int o = 16; o; o >>= 1) v = fmaxf(v, __shfl_xor_sync(0xffffffffu, v, o));
    return v;
}

// ================= helpers ==================================================
__device__ __forceinline__ uint32_t smem_u32(const void* p) {
    uint32_t a;
    asm("{ .reg .u64 t; cvta.to.shared.u64 t, %1; cvt.u32.u64 %0, t; }"
        : "=r"(a) : "l"(p));
    return a;
}
__device__ __forceinline__ void ldsm_x4(uint32_t* r, uint32_t addr) {
    asm volatile("ldmatrix.sync.aligned.m8n8.x4.shared.b16 {%0,%1,%2,%3}, [%4];"
                 : "=r"(r[0]), "=r"(r[1]), "=r"(r[2]), "=r"(r[3]) : "r"(addr));
}
__device__ __forceinline__ void ldsm_x2(uint32_t* r, uint32_t addr) {
    asm volatile("ldmatrix.sync.aligned.m8n8.x2.shared.b16 {%0,%1}, [%2];"
                 : "=r"(r[0]), "=r"(r[1]) : "r"(addr));
}
__device__ __forceinline__ void mma_f16(float* c, const uint32_t* a,
                                        const uint32_t* b) {
    asm volatile(
        "mma.sync.aligned.m16n8k16.row.col.f32.f16.f16.f32 "
        "{%0,%1,%2,%3}, {%4,%5,%6,%7}, {%8,%9}, {%0,%1,%2,%3};"
        : "+f"(c[0]), "+f"(c[1]), "+f"(c[2]), "+f"(c[3])
        : "r"(a[0]), "r"(a[1]), "r"(a[2]), "r"(a[3]), "r"(b[0]), "r"(b[1]));
}
__device__ __forceinline__ void cp16(uint32_t dst, const void* src) {
    asm volatile("cp.async.cg.shared.global [%0], [%1], 16;"
                 :: "r"(dst), "l"(src));
}
#define CP_COMMIT() asm volatile("cp.async.commit_group;" ::: "memory")
#define CP_WAIT0()  asm volatile("cp.async.wait_group 0;" ::: "memory")
#define CP_WAIT1()  asm volatile("cp.async.wait_group 1;" ::: "memory")

// ================ merged prelude: x-convert+gating | w-convert | cpb =========
__global__ void __launch_bounds__(256)
prelude(const float* __restrict__ x, const float* __restrict__ wg,
        const float* __restrict__ wg0, const float* __restrict__ wg1,
        const float* __restrict__ qw, const float* __restrict__ kvw,
        const float* __restrict__ srw, const float* __restrict__ pjw,
        const float* __restrict__ tbl, const float* __restrict__ w1,
        const float* __restrict__ b1, const float* __restrict__ w2,
        const float* __restrict__ b2) {
    const int bid = blockIdx.x;
    const int tid = threadIdx.x;
    if (bid < 2048) {
        // ---- conv_x_gate ----
        int t = bid * 8 + (tid >> 5);
        int lane = tid & 31;
        const float* xt = x + (size_t)t * CDIM;
        float4 xa = *(const float4*)(xt + lane * 8);
        float4 xb = *(const float4*)(xt + lane * 8 + 4);
        __half2 h0 = __floats2half2_rn(xa.x, xa.y);
        __half2 h1 = __floats2half2_rn(xa.z, xa.w);
        __half2 h2 = __floats2half2_rn(xb.x, xb.y);
        __half2 h3 = __floats2half2_rn(xb.z, xb.w);
        uint4 u;
        u.x = *(uint32_t*)&h0; u.y = *(uint32_t*)&h1;
        u.z = *(uint32_t*)&h2; u.w = *(uint32_t*)&h3;
        *(uint4*)(g_xh + (size_t)t * CDIM + lane * 8) = u;
        float d[10];
#pragma unroll
        for (int i = 0; i < 10; i++) {
            const float* wr = (i < 4) ? wg + i * CDIM
                            : (i < 8) ? wg1 + (i - 4) * CDIM
                                      : wg0 + (i - 8) * CDIM;
            float4 wa = *(const float4*)(wr + lane * 8);
            float4 wb = *(const float4*)(wr + lane * 8 + 4);
            float s = xa.x * wa.x + xa.y * wa.y + xa.z * wa.z + xa.w * wa.w
                    + xb.x * wb.x + xb.y * wb.y + xb.z * wb.z + xb.w * wb.w;
            d[i] = warp_sum(s);
        }
        float m0 = fmaxf(fmaxf(d[0], d[1]), fmaxf(d[2], d[3]));
        float e[4], se = 0.f;
#pragma unroll
        for (int i = 0; i < 4; i++) { e[i] = expf(d[i] - m0); se += e[i]; }
        float gsm[4];
#pragma unroll
        for (int i = 0; i < 4; i++) gsm[i] = e[i] / se;
        int i1 = 0;
#pragma unroll
        for (int i = 1; i < 4; i++) if (gsm[i] > gsm[i1]) i1 = i;
        int i2 = -1;
#pragma unroll
        for (int i = 0; i < 4; i++) {
            if (i == i1) continue;
            if (i2 < 0 || gsm[i] > gsm[i2]) i2 = i;
        }
        float rs = fmaxf(gsm[i1] + gsm[i2], EPSF);
        float routed[4];
#pragma unroll
        for (int i = 0; i < 4; i++)
            routed[i] = (i == i1 || i == i2) ? gsm[i] / rs * 2.f : 0.f;
        float m1 = fmaxf(fmaxf(d[4], d[5]), fmaxf(d[6], d[7]));
        float es[4], ss = 0.f;
#pragma unroll
        for (int i = 0; i < 4; i++) { es[i] = expf(d[4 + i] - m1); ss += es[i]; }
        float shg[4];
#pragma unroll
        for (int i = 0; i < 4; i++) shg[i] = es[i] / ss * 4.f;
        float m2 = fmaxf(d[8], d[9]);
        float e8 = expf(d[8] - m2), e9 = expf(d[9] - m2);
        float w00 = e8 / (e8 + e9) * 2.f;
        float w01 = e9 / (e8 + e9) * 2.f;
        if (lane < NH) {
            float v = (lane < 4) ? w00 * shg[lane] : w01 * routed[lane - 4];
            g_gate[(size_t)t * NH + lane] = v;
        }
    } else if (bid < 2368) {
        // ---- conv_w ----
        int i = (bid - 2048) * 256 + tid;   // float4 index
        int row = i >> 6;
        const float4* src;
        int off;
        if (row < 256)       { src = (const float4*)qw;  off = i; }
        else if (row < 768)  { src = (const float4*)kvw; off = i - 256 * 64; }
        else if (row < 1024) { src = (const float4*)srw; off = i - 768 * 64; }
        else                 { src = (const float4*)pjw; off = i - 1024 * 64; }
        float4 v = src[off];
        __half a0 = __float2half_rn(v.x), a1 = __float2half_rn(v.y);
        __half a2 = __float2half_rn(v.z), a3 = __float2half_rn(v.w);
        __half c0 = __float2half_rn(v.x - __half2float(a0));
        __half c1 = __float2half_rn(v.y - __half2float(a1));
        __half c2 = __float2half_rn(v.z - __half2float(a2));
        __half c3 = __float2half_rn(v.w - __half2float(a3));
        ushort4 H, L;
        H.x = *(uint16_t*)&a0; H.y = *(uint16_t*)&a1;
        H.z = *(uint16_t*)&a2; H.w = *(uint16_t*)&a3;
        L.x = *(uint16_t*)&c0; L.y = *(uint16_t*)&c1;
        L.z = *(uint16_t*)&c2; L.w = *(uint16_t*)&c3;
        ((ushort4*)g_wh)[i] = H;
        ((ushort4*)g_wl)[i] = L;
    } else {
        // ---- cpb: 2 table rows per block ----
        int sub = tid >> 7, t = tid & 127;
        int row = (bid - 2368) * 2 + sub;
        float t0 = tbl[row * 2 + 0], t1 = tbl[row * 2 + 1];
        float acc[8] = {};
        for (int j = t; j < 512; j += 128) {
            float hv = fmaxf(t0 * w1[2 * j] + t1 * w1[2 * j + 1] + b1[j], 0.f);
#pragma unroll
            for (int o = 0; o < 8; o++) acc[o] += hv * w2[o * 512 + j];
        }
#pragma unroll
        for (int o = 0; o < 8; o++) acc[o] = warp_sum(acc[o]);
        __shared__ float sh2[2][4][8];
        int wp = t >> 5, lane = t & 31;
        if (lane == 0)
#pragma unroll
            for (int o = 0; o < 8; o++) sh2[sub][wp][o] = acc[o];
        __syncthreads();
        if (t < 8)
            g_cpb[(size_t)row * 8 + t] =
                sh2[sub][0][t] + sh2[sub][1][t] + sh2[sub][2][t] +
                sh2[sub][3][t] + b2[t];
    }
}

// ================= 3-stage pipelined 2-term fp16 GEMM =======================
// MODE 0: fused q/kv/sr epilogues; `part` selects tiles: part 0 -> {Q,SR},
// part 1 -> {KV}.  MODE 1: plain.  MODE 2: pooled kv epilogue.
#define MATSZ (128 * 40)
#define STAGEB (3 * MATSZ * 2)
#define GSMEM (3 * STAGEB)          // 92160 B

template<int MODE>
__global__ void __launch_bounds__(256, 2)
gemm_f16(const __half* __restrict__ A,
         const __half* __restrict__ Wh, const __half* __restrict__ Wl,
         float* __restrict__ C0,
         const float* __restrict__ b0, const float* __restrict__ b1,
         const float* __restrict__ b2, int ldc0,
         const float* __restrict__ temp, const float* __restrict__ qe,
         int part) {
    extern __shared__ uint16_t sd[];
    int tile;
    if (MODE == 0)
        tile = (part == 0) ? ((int)blockIdx.x < 2 ? (int)blockIdx.x
                                                  : (int)blockIdx.x + 4)
                           : ((int)blockIdx.x + 2);
    else
        tile = blockIdx.x;
    const int bm = blockIdx.y * 128, bn = tile * 128;
    const int tid = threadIdx.x, lane = tid & 31, wid = tid >> 5;
    const int wm = (wid & 3) * 32, wn = (wid >> 2) * 64;
    float acc[2][8][4] = {};

    const __half* gsrc[3] = {
        A + (size_t)bm * 256, Wh + (size_t)bn * 256, Wl + (size_t)bn * 256};

    const int ldrow = tid >> 2, ldpart = tid & 3;
    const uint32_t sb0 = smem_u32(sd);
    uint32_t aAdr[2];
#pragma unroll
    for (int i = 0; i < 2; i++)
        aAdr[i] = sb0 + 2 * ((wm + i * 16 + (lane & 15)) * 40 + (lane >> 4) * 8);
    uint32_t bAdr[4];
    {
        int m = lane >> 3;
#pragma unroll
        for (int jp = 0; jp < 4; jp++)
            bAdr[jp] = sb0 + 2 * (MATSZ + (wn + jp * 16 + (m >> 1) * 8 +
                                           (lane & 7)) * 40 + (m & 1) * 8);
    }

#define GLOAD(stage, ko) do {                                                  \
    const int nb_ = (stage) * 3 * MATSZ;                                       \
    _Pragma("unroll")                                                          \
    for (int m_ = 0; m_ < 3; m_++)                                             \
        _Pragma("unroll")                                                      \
        for (int s_ = 0; s_ < 2; s_++) {                                       \
            int row_ = ldrow + s_ * 64;                                        \
            cp16(smem_u32(sd + nb_ + m_ * MATSZ + row_ * 40 + ldpart * 8),     \
                 gsrc[m_] + (size_t)row_ * 256 + (ko) + ldpart * 8);           \
        }                                                                      \
    CP_COMMIT();                                                               \
} while (0)

    GLOAD(0, 0);
    GLOAD(1, 32);

#pragma unroll
    for (int kc = 0; kc < 8; kc++) {
        const int stg = kc % 3;
        const uint32_t so = (uint32_t)stg * STAGEB;
        if (kc < 7) { CP_WAIT1(); } else { CP_WAIT0(); }
        __syncthreads();
        if (kc < 6) GLOAD((kc + 2) % 3, (kc + 2) * 32);
#pragma unroll
        for (int ks = 0; ks < 2; ks++) {
            const uint32_t so2 = so + ks * 32;
            uint32_t ah[2][4];
            ldsm_x4(ah[0], aAdr[0] + so2);
            ldsm_x4(ah[1], aAdr[1] + so2);
#pragma unroll
            for (int jp = 0; jp < 4; jp++) {
                uint32_t bh[4], bl[4];
                ldsm_x4(bh, bAdr[jp] + so2);
                ldsm_x4(bl, bAdr[jp] + so2 + 2 * MATSZ);
#pragma unroll
                for (int i = 0; i < 2; i++) {
                    mma_f16(acc[i][jp * 2], ah[i], bh);
                    mma_f16(acc[i][jp * 2], ah[i], bl);
                    mma_f16(acc[i][jp * 2 + 1], ah[i], bh + 2);
                    mma_f16(acc[i][jp * 2 + 1], ah[i], bl + 2);
                }
            }
        }
    }
#undef GLOAD

    if (MODE == 0) {
        const int r = bn >> 7;
        const bool isQ = r < 2, isK = (r == 2 || r == 3), isSR = r >= 6;
        const float* bias = isQ ? b0 : (r < 6 ? b1 : b2);
        const int cb = isQ ? bn : (r < 6 ? bn - 256 : bn - 768);
#pragma unroll
        for (int i = 0; i < 2; i++)
#pragma unroll
            for (int j = 0; j < 8; j++) {
                int col = cb + wn + j * 8 + (lane & 3) * 2;
                float bb0 = bias[col], bb1 = bias[col + 1];
                acc[i][j][0] += bb0; acc[i][j][1] += bb1;
                acc[i][j][2] += bb0; acc[i][j][3] += bb1;
                if (isSR) {
#pragma unroll
                    for (int t = 0; t < 4; t++) {
                        float v = acc[i][j][t];
                        acc[i][j][t] =
                            0.5f * v * (1.0f + erff(v * 0.70710678118654752f));
                    }
                }
            }
        if (isQ || isK) {
            float* sums = (float*)sd;
            sums[tid] = 0.f; sums[tid + 256] = 0.f;
            __syncthreads();
#pragma unroll
            for (int i = 0; i < 2; i++)
#pragma unroll
                for (int half = 0; half < 2; half++)
#pragma unroll
                    for (int hg = 0; hg < 2; hg++) {
                        float p = 0.f;
#pragma unroll
                        for (int j = hg * 4; j < hg * 4 + 4; j++)
                            p += acc[i][j][half * 2] * acc[i][j][half * 2] +
                                 acc[i][j][half * 2 + 1] * acc[i][j][half * 2 + 1];
                        p += __shfl_xor_sync(0xffffffffu, p, 1);
                        p += __shfl_xor_sync(0xffffffffu, p, 2);
                        if ((lane & 3) == 0) {
                            int rr = wm + i * 16 + (lane >> 2) + half * 8;
                            atomicAdd(&sums[rr * 4 + (wn >> 5) + hg], p);
                        }
                    }
            __syncthreads();
            if (isQ) {
                float sp[2];
#pragma unroll
                for (int hg = 0; hg < 2; hg++)
                    sp[hg] = log1pf(expf(temp[((bn + wn) >> 5) + hg]));
                float sls[2][2];
#pragma unroll
                for (int i = 0; i < 2; i++)
#pragma unroll
                    for (int half = 0; half < 2; half++) {
                        int row = wm + i * 16 + (lane >> 2) + half * 8;
                        int n = (bm + row) & (NTOK - 1);
                        int yq = n >> 6, xq = n & 63;
                        int chh = min(yq + 1, 63) - max(yq - 1, 0) + 1;
                        int cww = min(xq + 1, 63) - max(xq - 1, 0) + 1;
                        sls[i][half] = logf((float)(chh * cww + PLP));
                    }
#pragma unroll
                for (int i = 0; i < 2; i++)
#pragma unroll
                    for (int j = 0; j < 8; j++) {
                        int hg = j >> 2;
                        int gcol = bn + wn + j * 8 + (lane & 3) * 2;
                        float qe0 = qe[gcol];
                        float qe1 = qe[gcol + 1];
#pragma unroll
                        for (int half = 0; half < 2; half++) {
                            int row = wm + i * 16 + (lane >> 2) + half * 8;
                            float inv = 1.f /
                                fmaxf(sqrtf(sums[row * 4 + (wn >> 5) + hg]), EPSF);
                            float q0 = acc[i][j][half * 2] * inv;
                            float q1 = acc[i][j][half * 2 + 1] * inv;
                            size_t go = (size_t)(bm + row) * 256 + gcol;
                            float2 f2; f2.x = q0; f2.y = q1;
                            *(float2*)(g_q + go) = f2;
                            float m = sp[hg] * sls[i][half];
                            float s0 = (q0 + qe0) * m, s1 = (q1 + qe1) * m;
                            __half hh0 = __float2half_rn(s0);
                            __half hh1 = __float2half_rn(s1);
                            *(__half2*)(g_qsh + go) = __halves2half2(hh0, hh1);
                            *(__half2*)(g_qsl + go) = __halves2half2(
                                __float2half_rn(s0 - __half2float(hh0)),
                                __float2half_rn(s1 - __half2float(hh1)));
                        }
                    }
            } else {
#pragma unroll
                for (int i = 0; i < 2; i++)
#pragma unroll
                    for (int j = 0; j < 8; j++) {
                        int hg = j >> 2;
                        int gcol = cb + wn + j * 8 + (lane & 3) * 2;
#pragma unroll
                        for (int half = 0; half < 2; half++) {
                            int row = wm + i * 16 + (lane >> 2) + half * 8;
                            float inv = 1.f /
                                fmaxf(sqrtf(sums[row * 4 + (wn >> 5) + hg]), EPSF);
                            float2 f2;
                            f2.x = acc[i][j][half * 2] * inv;
                            f2.y = acc[i][j][half * 2 + 1] * inv;
                            *(float2*)(g_kv + (size_t)(bm + row) * 512 + gcol) = f2;
                        }
                    }
            }
        } else if (isSR) {
#pragma unroll
            for (int i = 0; i < 2; i++) {
                int r0 = bm + wm + i * 16 + (lane >> 2);
#pragma unroll
                for (int j = 0; j < 8; j++) {
                    int col = cb + wn + j * 8 + (lane & 3) * 2;
                    *(__half2*)(g_srh + (size_t)r0 * 256 + col) =
                        __floats2half2_rn(acc[i][j][0], acc[i][j][1]);
                    *(__half2*)(g_srh + (size_t)(r0 + 8) * 256 + col) =
                        __floats2half2_rn(acc[i][j][2], acc[i][j][3]);
                }
            }
        } else {
            // v tiles: plain fp32 store into g_kv second half
#pragma unroll
            for (int i = 0; i < 2; i++) {
                int r0 = bm + wm + i * 16 + (lane >> 2);
#pragma unroll
                for (int j = 0; j < 8; j++) {
                    int col = cb + wn + j * 8 + (lane & 3) * 2;
                    float2 o01; o01.x = acc[i][j][0]; o01.y = acc[i][j][1];
                    float2 o23; o23.x = acc[i][j][2]; o23.y = acc[i][j][3];
                    *(float2*)(g_kv + (size_t)r0 * 512 + col) = o01;
                    *(float2*)(g_kv + (size_t)(r0 + 8) * 512 + col) = o23;
                }
            }
        }
        return;
    }
    if (MODE == 2) {
        const bool isKp = bn < 256;
#pragma unroll
        for (int i = 0; i < 2; i++)
#pragma unroll
            for (int j = 0; j < 8; j++) {
                int col = bn + wn + j * 8 + (lane & 3) * 2;
                float bb0 = b0[col], bb1 = b0[col + 1];
                acc[i][j][0] += bb0; acc[i][j][1] += bb1;
                acc[i][j][2] += bb0; acc[i][j][3] += bb1;
            }
        if (isKp) {
            float* sums = (float*)sd;
            sums[tid] = 0.f; sums[tid + 256] = 0.f;
            __syncthreads();
#pragma unroll
            for (int i = 0; i < 2; i++)
#pragma unroll
                for (int half = 0; half < 2; half++)
#pragma unroll
                    for (int hg = 0; hg < 2; hg++) {
                        float p = 0.f;
#pragma unroll
                        for (int j = hg * 4; j < hg * 4 + 4; j++)
                            p += acc[i][j][half * 2] * acc[i][j][half * 2] +
                                 acc[i][j][half * 2 + 1] * acc[i][j][half * 2 + 1];
                        p += __shfl_xor_sync(0xffffffffu, p, 1);
                        p += __shfl_xor_sync(0xffffffffu, p, 2);
                        if ((lane & 3) == 0) {
                            int rr = wm + i * 16 + (lane >> 2) + half * 8;
                            atomicAdd(&sums[rr * 4 + (wn >> 5) + hg], p);
                        }
                    }
            __syncthreads();
#pragma unroll
            for (int i = 0; i < 2; i++)
#pragma unroll
                for (int j = 0; j < 8; j++) {
                    int hg = j >> 2;
                    int gcol = bn + wn + j * 8 + (lane & 3) * 2;
#pragma unroll
                    for (int half = 0; half < 2; half++) {
                        int row = wm + i * 16 + (lane >> 2) + half * 8;
                        float inv = 1.f /
                            fmaxf(sqrtf(sums[row * 4 + (wn >> 5) + hg]), EPSF);
                        float k0 = acc[i][j][half * 2] * inv;
                        float k1 = acc[i][j][half * 2 + 1] * inv;
                        __half hh0 = __float2half_rn(k0);
                        __half hh1 = __float2half_rn(k1);
                        size_t go = (size_t)(bm + row) * 256 + gcol;
                        *(__half2*)(g_kph + go) = __halves2half2(hh0, hh1);
                        *(__half2*)(g_kpl + go) = __halves2half2(
                            __float2half_rn(k0 - __half2float(hh0)),
                            __float2half_rn(k1 - __half2float(hh1)));
                    }
                }
        } else {
#pragma unroll
            for (int i = 0; i < 2; i++)
#pragma unroll
                for (int j = 0; j < 8; j++) {
                    int gcol = bn - 256 + wn + j * 8 + (lane & 3) * 2;
#pragma unroll
                    for (int half = 0; half < 2; half++) {
                        int row = wm + i * 16 + (lane >> 2) + half * 8;
                        *(__half2*)(g_vph + (size_t)(bm + row) * 256 + gcol) =
                            __floats2half2_rn(acc[i][j][half * 2],
                                              acc[i][j][half * 2 + 1]);
                    }
                }
        }
        return;
    }
    // MODE 1
#pragma unroll
    for (int i = 0; i < 2; i++) {
        int r0 = bm + wm + i * 16 + (lane >> 2);
#pragma unroll
        for (int j = 0; j < 8; j++) {
            int col = bn + wn + j * 8 + (lane & 3) * 2;
            float bb0 = b0[col], bb1 = b0[col + 1];
            float2 o01; o01.x = acc[i][j][0] + bb0; o01.y = acc[i][j][1] + bb1;
            float2 o23; o23.x = acc[i][j][2] + bb0; o23.y = acc[i][j][3] + bb1;
            *(float2*)(C0 + (size_t)r0 * ldc0 + col) = o01;
            *(float2*)(C0 + (size_t)(r0 + 8) * ldc0 + col) = o23;
        }
    }
}

// ---------------- 8x8 avg pool + LayerNorm (fp16 in, fp16 out) ---------------
__global__ void __launch_bounds__(256)
pool_ln(const float* __restrict__ gw, const float* __restrict__ gb) {
    int bp = blockIdx.x;
    int b = bp >> 6, p = bp & 63;
    int py = p >> 3, px = p & 7;
    int c = threadIdx.x;
    const __half* base = g_srh + (size_t)b * NTOK * CDIM;
    float s = 0.f;
    for (int iy = 0; iy < 8; iy++) {
        int y = py * 8 + iy;
        for (int ix = 0; ix < 8; ix++) {
            int n = y * RESHW + px * 8 + ix;
            s += __half2float(base[(size_t)n * CDIM + c]);
        }
    }
    float val = s * (1.0f / 64.0f);
    __shared__ float red[256];
    red[c] = val; __syncthreads();
    for (int st = 128; st > 0; st >>= 1) { if (c < st) red[c] += red[c + st]; __syncthreads(); }
    float mu = red[0] * (1.0f / 256.0f);
    __syncthreads();
    float dv = val - mu;
    red[c] = dv * dv; __syncthreads();
    for (int st = 128; st > 0; st >>= 1) { if (c < st) red[c] += red[c + st]; __syncthreads(); }
    float var = red[0] * (1.0f / 256.0f);
    float ov = dv * rsqrtf(var + 1e-5f) * gw[c] + gb[c];
    g_ph[(size_t)bp * CDIM + c] = __float2half_rn(ov);
}

// ================ pool logits via mma (S = Qs @ Kp^T, 3-term) ================
__global__ void __launch_bounds__(256)
pool_logits() {
    __shared__ __align__(16) uint16_t sQh[128 * 40];
    __shared__ __align__(16) uint16_t sQl[128 * 40];
    __shared__ __align__(16) uint16_t sKh[64 * 40];
    __shared__ __align__(16) uint16_t sKl[64 * 40];
    const int mtile = blockIdx.x, bh = blockIdx.y;
    const int b = bh >> 3, h = bh & 7;
    const int tid = threadIdx.x, lane = tid & 31, wid = tid >> 5;
    const int wm = wid * 16;
    const int n0 = mtile * 128;
    for (int i = tid; i < 512; i += 256) {
        int row = i >> 2, part = i & 3;
        size_t src = ((size_t)(b * NTOK + n0 + row)) * CDIM + h * HD + part * 8;
        cp16(smem_u32(sQh + row * 40 + part * 8), g_qsh + src);
        cp16(smem_u32(sQl + row * 40 + part * 8), g_qsl + src);
    }
    {
        int i = tid;
        if (i < 256) {
            int row = i >> 2, part = i & 3;
            size_t src = ((size_t)(b * PLP + row)) * CDIM + h * HD + part * 8;
            cp16(smem_u32(sKh + row * 40 + part * 8), g_kph + src);
            cp16(smem_u32(sKl + row * 40 + part * 8), g_kpl + src);
        }
    }
    CP_COMMIT(); CP_WAIT0();
    __syncthreads();
    float acc[8][4] = {};
#pragma unroll
    for (int ks = 0; ks < 2; ks++) {
        uint32_t qh[4], ql[4];
        const int arow = lane & 15, acol = ks * 16 + (lane >> 4) * 8;
        ldsm_x4(qh, smem_u32(sQh + (wm + arow) * 40 + acol));
        ldsm_x4(ql, smem_u32(sQl + (wm + arow) * 40 + acol));
        const int brow0 = lane & 7;
        const int bcol = ks * 16 + ((lane >> 3) & 1) * 8;
#pragma unroll
        for (int j = 0; j < 8; j++) {
            uint32_t kh[2], kl[2];
            ldsm_x2(kh, smem_u32(sKh + (brow0 + j * 8) * 40 + bcol));
            ldsm_x2(kl, smem_u32(sKl + (brow0 + j * 8) * 40 + bcol));
            mma_f16(acc[j], qh, kh);
            mma_f16(acc[j], ql, kh);
            mma_f16(acc[j], qh, kl);
        }
    }
    int r0 = n0 + wm + (lane >> 2);
#pragma unroll
    for (int j = 0; j < 8; j++) {
        int col = j * 8 + (lane & 3) * 2;
        float2 a; a.x = acc[j][0]; a.y = acc[j][1];
        float2 c; c.x = acc[j][2]; c.y = acc[j][3];
        *(float2*)(g_spool + ((size_t)bh * NTOK + r0) * PLP + col) = a;
        *(float2*)(g_spool + ((size_t)bh * NTOK + r0 + 8) * PLP + col) = c;
    }
}

// ================ attn: local logits + softmax + local AV + fused P@Vp =======
#define AKW 0
#define AVW 3366
#define AQS 6732
#define AQN 7788
#define ALG 8844
#define ALT 11532
#define ALO 11832
#define AFLOATS 12888
#define ASMEMB (AFLOATS * 4 + 3 * 2304 * 2)   // 65376 B

__global__ void __launch_bounds__(1024)
attn_soft(const float* __restrict__ rpb, const float* __restrict__ lt,
          const float* __restrict__ lb, const int* __restrict__ rel_idx) {
    extern __shared__ float sh[];
    float* Kw  = sh + AKW;     // [102][33]
    float* Vw  = sh + AVW;
    float* qss = sh + AQS;     // [32][33]
    float* qns = sh + AQN;
    float* lg  = sh + ALG;     // [32][84]
    float* lts = sh + ALT;     // [9][33]
    float* lout = sh + ALO;    // [32][33]
    __half* Ph = (__half*)(sh + AFLOATS);   // [32][72]
    __half* Pl = Ph + 2304;
    __half* Vt = Pl + 2304;                 // [32][72] (d-major)
    int blk = blockIdx.x;
    int ntile = blk & 127;
    int hh = (blk >> 7) & 7;
    int b = blk >> 10;
    int bh = b * 8 + hh;
    int tid = threadIdx.x, w = tid >> 5, lane = tid & 31;
    int y = ntile >> 1, x0 = (ntile & 1) << 5;

    for (int i = tid; i < 3264; i += 1024) {
        int vec = i >> 5, d = i & 31;
        int r = vec / 34, c = vec - r * 34;
        int yy = y + r - 1, xx = x0 - 1 + c;
        float kv0 = 0.f, vv0 = 0.f;
        if ((unsigned)yy < 64u && (unsigned)xx < 64u) {
            size_t base = ((size_t)(b * NTOK + yy * 64 + xx)) * 512 + hh * 32 + d;
            kv0 = g_kv[base];
            vv0 = g_kv[base + 256];
        }
        Kw[vec * 33 + d] = kv0;
        Vw[vec * 33 + d] = vv0;
    }
    if (tid < 288) {
        int d = tid / 9, l = tid - d * 9;
        lts[l * 33 + d] = lt[hh * 288 + tid];
    }
    for (int i = tid; i < 2048; i += 1024) {
        int p = i >> 5, d = i & 31;
        Vt[d * 72 + p] =
            g_vph[((size_t)(b * PLP + p)) * CDIM + hh * HD + d];
    }
    int n = ntile * 32 + w;
    size_t qoff = ((size_t)(b * NTOK + n)) * 256 + hh * 32 + lane;
    qss[w * 33 + lane] = __half2float(g_qsh[qoff]) + __half2float(g_qsl[qoff]);
    qns[w * 33 + lane] = g_q[qoff];
    __syncthreads();

    int xl = n & 31;
    const int* rix = rel_idx + (size_t)n * 64;
    {
        int o = lane;
        if (o < 18) {
            const float* kr;
            const float* qr;
            float bias;
            int slot;
            if (o < 9) {
                int r = o / 3, dc = o - r * 3;
                kr = Kw + (r * 34 + xl + dc) * 33;
                qr = qss + w * 33;
                bias = rpb[hh * 9 + o];
                slot = 64 + o;
            } else {
                int l = o - 9;
                kr = lts + l * 33;
                qr = qns + w * 33;
                bias = lb[hh * 9 + l];
                slot = 73 + l;
            }
            float acc = bias;
#pragma unroll
            for (int d = 0; d < 32; d++) acc += qr[d] * kr[d];
            lg[w * 84 + slot] = acc;
        }
    }
    __syncwarp();
    size_t soff = ((size_t)bh * NTOK + n) * 64;
    float s0 = g_spool[soff + lane] + g_cpb[(size_t)rix[lane] * 8 + hh];
    float s1 = g_spool[soff + 32 + lane] + g_cpb[(size_t)rix[lane + 32] * 8 + hh];
    float l0 = (lane < 9) ? lg[w * 84 + 64 + lane] : -3.4e38f;
    float mx = warp_max(fmaxf(fmaxf(s0, s1), l0));
    float e0 = expf(s0 - mx), e1 = expf(s1 - mx);
    float e2 = (lane < 9) ? expf(l0 - mx) : 0.f;
    float inv = 1.0f / warp_sum(e0 + e1 + e2);
    float p0 = e0 * inv, p1 = e1 * inv;
    __half p0h = __float2half_rn(p0);
    __half p1h = __float2half_rn(p1);
    Ph[w * 72 + lane] = p0h;
    Pl[w * 72 + lane] = __float2half_rn(p0 - __half2float(p0h));
    Ph[w * 72 + 32 + lane] = p1h;
    Pl[w * 72 + 32 + lane] = __float2half_rn(p1 - __half2float(p1h));
    if (lane < 9) lg[w * 84 + lane] = e2 * inv + lg[w * 84 + 73 + lane];
    __syncwarp();
    float outv = 0.f;
#pragma unroll
    for (int l = 0; l < 9; l++) {
        int r = l / 3, dc = l - r * 3;
        outv += lg[w * 84 + l] * Vw[(r * 34 + xl + dc) * 33 + lane];
    }
    lout[w * 33 + lane] = outv;
    __syncthreads();

    if (w < 8) {
        const int mtile = w >> 2, j = w & 3;
        float acc[4] = {};
#pragma unroll
        for (int kc = 0; kc < 4; kc++) {
            uint32_t ph[4], pl[4], bv[2];
            uint32_t aoff = (uint32_t)((mtile * 16 + (lane & 15)) * 72 +
                                       kc * 16 + (lane >> 4) * 8);
            ldsm_x4(ph, smem_u32(Ph + aoff));
            ldsm_x4(pl, smem_u32(Pl + aoff));
            ldsm_x2(bv, smem_u32(Vt + ((lane & 7) + j * 8) * 72 +
                                 kc * 16 + ((lane >> 3) & 1) * 8));
            mma_f16(acc, ph, bv);
            mma_f16(acc, pl, bv);
        }
        const int d = j * 8 + (lane & 3) * 2;
#pragma unroll
        for (int hf = 0; hf < 2; hf++) {
            int wloc = mtile * 16 + (lane >> 2) + hf * 8;
            int nn = ntile * 32 + wloc;
            float lo0 = lout[wloc * 33 + d];
            float lo1 = lout[wloc * 33 + d + 1];
            float gt = g_gate[((size_t)(b * NTOK + nn)) * 8 + hh];
            float o0 = (acc[hf * 2 + 0] + lo0) * gt;
            float o1 = (acc[hf * 2 + 1] + lo1) * gt;
            *(__half2*)(g_ah + ((size_t)(b * NTOK + nn)) * CDIM + hh * HD + d) =
                __floats2half2_rn(o0, o1);
        }
    }
}

// ---------------- launch ----------------------------------------------------
extern "C" void kernel_launch(void* const* d_in, const int* in_sizes, int n_in,
                              void* d_out, int out_size) {
    const float* x      = (const float*)d_in[0];
    const float* rct    = (const float*)d_in[1];
    const float* q_w    = (const float*)d_in[2];
    const float* q_b    = (const float*)d_in[3];
    const float* kv_w   = (const float*)d_in[4];
    const float* kv_b   = (const float*)d_in[5];
    const float* temp   = (const float*)d_in[6];
    const float* qe     = (const float*)d_in[7];
    const float* rpb    = (const float*)d_in[8];
    const float* lt     = (const float*)d_in[9];
    const float* lb     = (const float*)d_in[10];
    const float* cpb1_w = (const float*)d_in[11];
    const float* cpb1_b = (const float*)d_in[12];
    const float* cpb2_w = (const float*)d_in[13];
    const float* cpb2_b = (const float*)d_in[14];
    const float* sr_w   = (const float*)d_in[15];
    const float* sr_b   = (const float*)d_in[16];
    const float* norm_g = (const float*)d_in[17];
    const float* norm_b = (const float*)d_in[18];
    const float* wg_w   = (const float*)d_in[19];
    const float* wg0_w  = (const float*)d_in[20];
    const float* wg1_w  = (const float*)d_in[21];
    const float* proj_w = (const float*)d_in[22];
    const float* proj_b = (const float*)d_in[23];
    const int*   ridx   = (const int*)d_in[24];
    float* out = (float*)d_out;

    __half *pxh, *pwh, *pwl, *pph, *pah;
    cudaGetSymbolAddress((void**)&pxh,  g_xh);
    cudaGetSymbolAddress((void**)&pwh,  g_wh);
    cudaGetSymbolAddress((void**)&pwl,  g_wl);
    cudaGetSymbolAddress((void**)&pph,  g_ph);
    cudaGetSymbolAddress((void**)&pah,  g_ah);

    cudaFuncSetAttribute(gemm_f16<0>,
                         cudaFuncAttributeMaxDynamicSharedMemorySize, GSMEM);
    cudaFuncSetAttribute(gemm_f16<1>,
                         cudaFuncAttributeMaxDynamicSharedMemorySize, GSMEM);
    cudaFuncSetAttribute(gemm_f16<2>,
                         cudaFuncAttributeMaxDynamicSharedMemorySize, GSMEM);
    cudaFuncSetAttribute(attn_soft,
                         cudaFuncAttributeMaxDynamicSharedMemorySize, ASMEMB);

    // side stream + events, created once on the first (uncaptured) call
    static cudaStream_t s2 = nullptr;
    static cudaEvent_t ev1 = nullptr, ev2 = nullptr;
    if (s2 == nullptr) {
        cudaStreamCreateWithFlags(&s2, cudaStreamNonBlocking);
        cudaEventCreateWithFlags(&ev1, cudaEventDisableTiming);
        cudaEventCreateWithFlags(&ev2, cudaEventDisableTiming);
    }

    const int M = BATCH * NTOK;                       // 16384

    prelude<<<4416, 256>>>(x, wg_w, wg0_w, wg1_w, q_w, kv_w, sr_w, proj_w,
                           rct, cpb1_w, cpb1_b, cpb2_w, cpb2_b);
    // gemm0 part 0: Q + SR tiles
    dim3 gqsr(4, M / 128);
    gemm_f16<0><<<gqsr, 256, GSMEM>>>(pxh, pwh, pwl, nullptr,
                                      q_b, kv_b, sr_b, 0, temp, qe, 0);
    cudaEventRecord(ev1, 0);
    // gemm0 part 1: KV tiles (main stream, overlapped with side chain)
    gemm_f16<0><<<gqsr, 256, GSMEM>>>(pxh, pwh, pwl, nullptr,
                                      q_b, kv_b, sr_b, 0, temp, qe, 1);
    // side chain: pool_ln -> pooled gemm -> pool_logits
    cudaStreamWaitEvent(s2, ev1, 0);
    pool_ln<<<BATCH * PLP, 256, 0, s2>>>(norm_g, norm_b);
    dim3 gp(4, 2);
    gemm_f16<2><<<gp, 256, GSMEM, s2>>>(pph, pwh + 256 * 256, pwl + 256 * 256,
                                        nullptr, kv_b, nullptr, nullptr, 0,
                                        nullptr, nullptr, -1);
    dim3 ga(NTOK / 128, BH);
    pool_logits<<<ga, 256, 0, s2>>>();
    cudaEventRecord(ev2, s2);
    // join and finish on main stream
    cudaStreamWaitEvent(0, ev2, 0);
    attn_soft<<<BATCH * NH * (NTOK / 32), 1024, ASMEMB>>>(rpb, lt, lb, ridx);
    dim3 gj(2, M / 128);
    gemm_f16<1><<<gj, 256, GSMEM>>>(pah, pwh + 1024 * 256, pwl + 1024 * 256,
                                    out, proj_b, nullptr, nullptr, 256,
                                    nullptr, nullptr, -1);
}